// round 10
// baseline (speedup 1.0000x reference)
#include <cuda_runtime.h>
#include <cuda_fp16.h>

// ---------------------------------------------------------------------------
// Problem constants
// ---------------------------------------------------------------------------
#define N_NODES 4096
#define AGGW    1024     // K(16) * WIDTH(64)
#define KSPLIT  8

// ---------------------------------------------------------------------------
// Packed f32x2 helpers (sm_103a FFMA2 path)
// ---------------------------------------------------------------------------
__device__ __forceinline__ unsigned long long ffma2(unsigned long long a,
                                                    unsigned long long b,
                                                    unsigned long long c) {
    unsigned long long d;
    asm("fma.rn.f32x2 %0, %1, %2, %3;" : "=l"(d) : "l"(a), "l"(b), "l"(c));
    return d;
}
__device__ __forceinline__ unsigned long long fpack2(float lo, float hi) {
    unsigned long long r;
    asm("mov.b64 %0, {%1, %2};" : "=l"(r) : "f"(lo), "f"(hi));
    return r;
}
__device__ __forceinline__ float2 funpack2(unsigned long long v) {
    float lo, hi;
    asm("mov.b64 {%0, %1}, %2;" : "=f"(lo), "=f"(hi) : "l"(v));
    return make_float2(lo, hi);
}

// ---------------------------------------------------------------------------
// Scratch (device globals -- no allocation allowed). 16B-aligned for float4.
// ---------------------------------------------------------------------------
__device__ __align__(16) float g_h0[N_NODES * 64];
__device__ __align__(16) __half g_agg1[N_NODES * AGGW];
__device__ __align__(16) __half g_agg2[N_NODES * AGGW];
__device__ __align__(16) __half g_agg3[N_NODES * AGGW];
__device__ __align__(16) float g_cat[N_NODES * 64];
__device__ __align__(16) float g_part[KSPLIT * N_NODES * 64];   // split-K partials
// partial column stats: x: 16 slots * 256 = 4096
//                       h0: 64 slots * 128 = 8192 at offset 4096
//                       cat: 64 slots * 128 = 8192 at offset 12288
__device__ float g_stats[20480];
__device__ float g_sb[128];          // mid-BN folded scale[0:64) / bias[64:128)
__device__ int   g_ro[N_NODES + 1];

// ---------------------------------------------------------------------------
// BN fold: reduce nslots partial (sum, sq) -> per-channel scale/bias in smem
// ---------------------------------------------------------------------------
__device__ __forceinline__ void bn_fold(const float* __restrict__ stats, int C,
                                        int nslots,
                                        const float* __restrict__ g,
                                        const float* __restrict__ b,
                                        float* s_sc, float* s_bi,
                                        int t, int nthreads) {
    for (int c = t; c < C; c += nthreads) {
        float s = 0.0f, q = 0.0f;
        for (int bk = 0; bk < nslots; bk++) {
            s += stats[bk * 2 * C + c];
            q += stats[bk * 2 * C + C + c];
        }
        float m = s * (1.0f / N_NODES);
        float v = q * (1.0f / N_NODES) - m * m;
        float rs = rsqrtf(v + 1e-5f);
        float sc = rs * g[c];
        s_sc[c] = sc;
        s_bi[c] = b[c] - m * sc;
    }
}

// ---------------------------------------------------------------------------
// fold_bn_k: one block, folds the 64-slot h0 stats into g_sb once
// (removes 33M redundant loads from edge_all's 4096 blocks)
// ---------------------------------------------------------------------------
__global__ void fold_bn_k(const float* __restrict__ stats,
                          const float* __restrict__ g,
                          const float* __restrict__ b,
                          float* __restrict__ sb) {
    int c = threadIdx.x;   // 64 threads
    float s = 0.0f, q = 0.0f;
    for (int bk = 0; bk < 64; bk++) {
        s += stats[bk * 128 + c];
        q += stats[bk * 128 + 64 + c];
    }
    float m = s * (1.0f / N_NODES);
    float v = q * (1.0f / N_NODES) - m * m;
    float rs = rsqrtf(v + 1e-5f);
    float sc = rs * g[c];
    sb[c] = sc;
    sb[64 + c] = b[c] - m * sc;
}

// ---------------------------------------------------------------------------
// prep: blocks 0..15 -> partial column stats of x (C=128)
//       blocks 16..32 -> CSR row offsets for branch-1 dst (binary search)
// ---------------------------------------------------------------------------
__global__ void prep_k(const float* __restrict__ x, const int* __restrict__ dst,
                       int E, float* __restrict__ stats_x, int* __restrict__ ro) {
    int bx = blockIdx.x;
    if (bx < 16) {
        int c = threadIdx.x;
        if (c < 128) {
            int r0 = bx * 256;
            float s = 0.0f, s2 = 0.0f;
            for (int r = r0; r < r0 + 256; r++) {
                float v = x[(size_t)r * 128 + c];
                s += v;
                s2 += v * v;
            }
            stats_x[bx * 256 + c] = s;
            stats_x[bx * 256 + 128 + c] = s2;
        }
    } else {
        int t = (bx - 16) * 256 + threadIdx.x;
        if (t > N_NODES) return;
        if (t == N_NODES) { ro[t] = E; return; }
        int lo = 0, hi = E;
        while (lo < hi) {
            int mid = (lo + hi) >> 1;
            if (dst[mid] < t) lo = mid + 1; else hi = mid;
        }
        ro[t] = lo;
    }
}

// ---------------------------------------------------------------------------
// gemm_x: merged identity + input GEMMs on A = x [4096,128].
// ---------------------------------------------------------------------------
__global__ __launch_bounds__(256) void gemm_x_k(
    const float* __restrict__ x, const float* __restrict__ stats_x,
    const float* __restrict__ id_g, const float* __restrict__ id_b,
    const float* __restrict__ idW,
    const float* __restrict__ in_g, const float* __restrict__ in_b,
    const float* __restrict__ inW,
    float* __restrict__ out, float* __restrict__ h0,
    float* __restrict__ stats_h) {
    __shared__ float s_sc[128], s_bi[128];
    __shared__ __align__(16) float As[16][65];
    __shared__ __align__(16) float Bs[16][64];
    __shared__ float hs[64], hq[64];
    int t = threadIdx.x;
    int bx = blockIdx.x;
    bool idp = bx < 4;
    bn_fold(stats_x, 128, 16, idp ? id_g : in_g, idp ? id_b : in_b, s_sc, s_bi, t, 256);

    const float* B = idp ? idW : inW;
    int Nd = idp ? 256 : 64;
    int n0 = idp ? bx * 64 : 0;
    float* C = idp ? out : h0;
    int m0 = blockIdx.y * 64;
    int tx = t & 15, ty = t >> 4;
    int lam = t >> 2, lak = (t & 3) << 2;
    int lbk = t >> 4, lbn = (t & 15) << 2;
    float acc[4][4];
#pragma unroll
    for (int r = 0; r < 4; r++)
#pragma unroll
        for (int cc = 0; cc < 4; cc++) acc[r][cc] = 0.0f;
    if (t < 64) { hs[t] = 0.0f; hq[t] = 0.0f; }
    __syncthreads();

    for (int k0 = 0; k0 < 128; k0 += 16) {
        float4 av = *(const float4*)(x + (size_t)(m0 + lam) * 128 + k0 + lak);
        float v;
        v = av.x * s_sc[k0 + lak + 0] + s_bi[k0 + lak + 0]; av.x = v > 0.0f ? v : 0.1f * v;
        v = av.y * s_sc[k0 + lak + 1] + s_bi[k0 + lak + 1]; av.y = v > 0.0f ? v : 0.1f * v;
        v = av.z * s_sc[k0 + lak + 2] + s_bi[k0 + lak + 2]; av.z = v > 0.0f ? v : 0.1f * v;
        v = av.w * s_sc[k0 + lak + 3] + s_bi[k0 + lak + 3]; av.w = v > 0.0f ? v : 0.1f * v;
        As[lak + 0][lam] = av.x;
        As[lak + 1][lam] = av.y;
        As[lak + 2][lam] = av.z;
        As[lak + 3][lam] = av.w;
        float4 bv = *(const float4*)(B + (size_t)(k0 + lbk) * Nd + n0 + lbn);
        *(float4*)&Bs[lbk][lbn] = bv;
        __syncthreads();
#pragma unroll
        for (int kk = 0; kk < 16; kk++) {
            float a0 = As[kk][ty * 4 + 0];
            float a1 = As[kk][ty * 4 + 1];
            float a2 = As[kk][ty * 4 + 2];
            float a3 = As[kk][ty * 4 + 3];
            float4 b = *(const float4*)&Bs[kk][tx * 4];
            acc[0][0] += a0 * b.x; acc[0][1] += a0 * b.y; acc[0][2] += a0 * b.z; acc[0][3] += a0 * b.w;
            acc[1][0] += a1 * b.x; acc[1][1] += a1 * b.y; acc[1][2] += a1 * b.z; acc[1][3] += a1 * b.w;
            acc[2][0] += a2 * b.x; acc[2][1] += a2 * b.y; acc[2][2] += a2 * b.z; acc[2][3] += a2 * b.w;
            acc[3][0] += a3 * b.x; acc[3][1] += a3 * b.y; acc[3][2] += a3 * b.z; acc[3][3] += a3 * b.w;
        }
        __syncthreads();
    }
#pragma unroll
    for (int r = 0; r < 4; r++) {
        int m = m0 + ty * 4 + r;
#pragma unroll
        for (int cc = 0; cc < 4; cc++)
            C[(size_t)m * Nd + n0 + tx * 4 + cc] = acc[r][cc];
    }
    if (!idp) {
#pragma unroll
        for (int cc = 0; cc < 4; cc++) {
            float s = acc[0][cc] + acc[1][cc] + acc[2][cc] + acc[3][cc];
            float q = acc[0][cc] * acc[0][cc] + acc[1][cc] * acc[1][cc] +
                      acc[2][cc] * acc[2][cc] + acc[3][cc] * acc[3][cc];
            atomicAdd(&hs[tx * 4 + cc], s);
            atomicAdd(&hq[tx * 4 + cc], q);
        }
        __syncthreads();
        if (t < 64) {
            stats_h[blockIdx.y * 128 + t] = hs[t];
            stats_h[blockIdx.y * 128 + 64 + t] = hq[t];
        }
    }
}

// ---------------------------------------------------------------------------
// Fused edge aggregation for ALL THREE branches in one pass over branch-1 CSR.
// R9 structure + (a) pre-folded mid-BN from g_sb, (b) Ws/bs staged in smem.
// ---------------------------------------------------------------------------
#define EB 32
__global__ __launch_bounds__(256) void edge_all_k(
    const float* __restrict__ h0, const float* __restrict__ pos,
    const float* __restrict__ ori, const int* __restrict__ seq,
    const int* __restrict__ src, const int* __restrict__ ro,
    const float* __restrict__ Ws1, const float* __restrict__ bs1,
    const float* __restrict__ Ws2, const float* __restrict__ bs2,
    const float* __restrict__ Ws3, const float* __restrict__ bs3,
    const float* __restrict__ sb,
    __half* __restrict__ agg1, __half* __restrict__ agg2,
    __half* __restrict__ agg3) {
    const double R2SQ = 1.8 * 1.8;
    const double R3T  = 0.75 * 1.8;
    const double R3SQ = R3T * R3T;
    __shared__ float s_sc[64], s_bi[64];
    __shared__ float s_W1[5 * 112],  s_b1[5 * 16];
    __shared__ float s_W2[7 * 112],  s_b2[7 * 16];
    __shared__ float s_W3[11 * 112], s_b3[11 * 16];
    __shared__ float s_fri[9];
    __shared__ float s_posi[3];
    __shared__ int   s_seqi;
    __shared__ float s_d[EB];
    __shared__ int   s_in2[EB], s_in3[EB];
    __shared__ float s_feat[EB][6];
    __shared__ int   s_ds[EB], s_src[EB];
    __shared__ __align__(16) unsigned long long s_wp[EB][16][4]; // {w1,w1}{w2,w2}{w3,w3}pad
    __shared__ __align__(16) float s_h[EB][64];

    int i = blockIdx.x;
    int t = threadIdx.x;
    // stage pre-folded BN + all filter weights into shared
    if (t < 128) { if (t < 64) s_sc[t] = sb[t]; else s_bi[t - 64] = sb[t]; }
    for (int j = t; j < 5 * 112; j += 256)  s_W1[j] = Ws1[j];
    for (int j = t; j < 5 * 16; j += 256)   s_b1[j] = bs1[j];
    for (int j = t; j < 7 * 112; j += 256)  s_W2[j] = Ws2[j];
    for (int j = t; j < 7 * 16; j += 256)   s_b2[j] = bs2[j];
    for (int j = t; j < 11 * 112; j += 256) s_W3[j] = Ws3[j];
    for (int j = t; j < 11 * 16; j += 256)  s_b3[j] = bs3[j];
    if (t < 9)  s_fri[t] = ori[i * 9 + t];
    if (t >= 9 && t < 12) s_posi[t - 9] = pos[i * 3 + (t - 9)];
    if (t == 12) s_seqi = seq[i];

    int start = ro[i], end = ro[i + 1];
    unsigned long long A1lo = 0ull, A1hi = 0ull;
    unsigned long long A2lo = 0ull, A2hi = 0ull;
    unsigned long long A3lo = 0ull, A3hi = 0ull;
    int k = t >> 4, c0 = (t & 15) << 2;
    __syncthreads();

    for (int e0 = start; e0 < end; e0 += EB) {
        int ne = min(EB, end - e0);
        // --- Phase A: per-edge geometry (1 thread per edge) ---
        if (t < ne) {
            int js = src[e0 + t];
            s_src[t] = js;
            float dx = __fadd_rn(pos[js * 3 + 0], -s_posi[0]);
            float dy = __fadd_rn(pos[js * 3 + 1], -s_posi[1]);
            float dz = __fadd_rn(pos[js * 3 + 2], -s_posi[2]);
            float d2 = __fadd_rn(__fadd_rn(__fmul_rn(dx, dx), __fmul_rn(dy, dy)),
                                 __fmul_rn(dz, dz));
            double d2d = (double)d2;
            s_in2[t] = (d2d <= R2SQ) ? 1 : 0;
            s_in3[t] = (d2d <= R3SQ) ? 1 : 0;
            float dist = sqrtf(d2);
            s_d[t] = dist;
            float inv = 1.0f / (dist + 1e-9f);
            float ux = dx * inv, uy = dy * inv, uz = dz * inv;
            float f0 = s_fri[0], f1 = s_fri[1], f2 = s_fri[2];
            float f3 = s_fri[3], f4 = s_fri[4], f5 = s_fri[5];
            float f6 = s_fri[6], f7 = s_fri[7], f8 = s_fri[8];
            s_feat[t][0] = f0 * ux + f1 * uy + f2 * uz;
            s_feat[t][1] = f3 * ux + f4 * uy + f5 * uz;
            s_feat[t][2] = f6 * ux + f7 * uy + f8 * uz;
            const float* op = ori + (size_t)js * 9;
            s_feat[t][3] = f0 * op[0] + f1 * op[1] + f2 * op[2];
            s_feat[t][4] = f3 * op[3] + f4 * op[4] + f5 * op[5];
            s_feat[t][5] = f6 * op[6] + f7 * op[7] + f8 * op[8];
            s_ds[t] = seq[js] - s_seqi;
        }
        __syncthreads();
        // --- Phase B1: edge weights per branch (weights from smem) ---
        for (int task = t; task < ne * 16; task += 256) {   // branch 1
            int e = task >> 4, kk = task & 15;
            int d = s_ds[e]; d = max(-2, min(2, d));
            int idx = d + 2;
            const float* wr = s_W1 + idx * 112 + kk;
            float s = s_b1[idx * 16 + kk] + (s_d[e] / 2.7f) * wr[0];
#pragma unroll
            for (int cc = 0; cc < 6; cc++) s += s_feat[e][cc] * wr[(cc + 1) * 16];
            s = s > 0.0f ? s : 0.2f * s;
            s_wp[e][kk][0] = fpack2(s, s);
        }
        for (int task = t; task < ne * 16; task += 256) {   // branch 2
            int e = task >> 4, kk = task & 15;
            float w = 0.0f;
            if (s_in2[e]) {
                int d = s_ds[e]; d = max(-3, min(3, d));
                int idx = d + 3;
                const float* wr = s_W2 + idx * 112 + kk;
                float s = s_b2[idx * 16 + kk] + (s_d[e] / 1.8f) * wr[0];
#pragma unroll
                for (int cc = 0; cc < 6; cc++) s += s_feat[e][cc] * wr[(cc + 1) * 16];
                w = s > 0.0f ? s : 0.2f * s;
            }
            s_wp[e][kk][1] = fpack2(w, w);
        }
        for (int task = t; task < ne * 16; task += 256) {   // branch 3
            int e = task >> 4, kk = task & 15;
            float w = 0.0f;
            if (s_in3[e]) {
                int d = s_ds[e]; d = max(-5, min(5, d));
                int idx = d + 5;
                const float* wr = s_W3 + idx * 112 + kk;
                float s = s_b3[idx * 16 + kk] + (s_d[e] / 1.35f) * wr[0];
#pragma unroll
                for (int cc = 0; cc < 6; cc++) s += s_feat[e][cc] * wr[(cc + 1) * 16];
                w = s > 0.0f ? s : 0.2f * s;
            }
            s_wp[e][kk][2] = fpack2(w, w);
        }
        // --- Phase B2: gather h0 rows with mid-BN + lrelu folded in ---
        for (int task = t; task < ne * 16; task += 256) {
            int e = task >> 4, q = task & 15;
            int cc = q << 2;
            float4 v = *(const float4*)(h0 + (size_t)s_src[e] * 64 + cc);
            float u;
            u = v.x * s_sc[cc + 0] + s_bi[cc + 0]; v.x = u > 0.0f ? u : 0.1f * u;
            u = v.y * s_sc[cc + 1] + s_bi[cc + 1]; v.y = u > 0.0f ? u : 0.1f * u;
            u = v.z * s_sc[cc + 2] + s_bi[cc + 2]; v.z = u > 0.0f ? u : 0.1f * u;
            u = v.w * s_sc[cc + 3] + s_bi[cc + 3]; v.w = u > 0.0f ? u : 0.1f * u;
            *(float4*)&s_h[e][cc] = v;
        }
        __syncthreads();
        // --- Phase C: packed rank-1 accumulate: 3 LDS + 6 FFMA2 per edge ---
        for (int e = 0; e < ne; e++) {
            ulonglong2 h2 = *(const ulonglong2*)&s_h[e][c0];
            ulonglong2 w12 = *(const ulonglong2*)&s_wp[e][k][0];
            unsigned long long w3p = s_wp[e][k][2];
            A1lo = ffma2(w12.x, h2.x, A1lo); A1hi = ffma2(w12.x, h2.y, A1hi);
            A2lo = ffma2(w12.y, h2.x, A2lo); A2hi = ffma2(w12.y, h2.y, A2hi);
            A3lo = ffma2(w3p,  h2.x, A3lo); A3hi = ffma2(w3p,  h2.y, A3hi);
        }
        __syncthreads();
    }
    size_t off = (size_t)i * AGGW + k * 64 + c0;
    {
        float2 lo = funpack2(A1lo), hi = funpack2(A1hi);
        union { __half2 h2[2]; uint2 u; } cv;
        cv.h2[0] = __float22half2_rn(lo);
        cv.h2[1] = __float22half2_rn(hi);
        *(uint2*)(agg1 + off) = cv.u;
    }
    {
        float2 lo = funpack2(A2lo), hi = funpack2(A2hi);
        union { __half2 h2[2]; uint2 u; } cv;
        cv.h2[0] = __float22half2_rn(lo);
        cv.h2[1] = __float22half2_rn(hi);
        *(uint2*)(agg2 + off) = cv.u;
    }
    {
        float2 lo = funpack2(A3lo), hi = funpack2(A3hi);
        union { __half2 h2[2]; uint2 u; } cv;
        cv.h2[0] = __float22half2_rn(lo);
        cv.h2[1] = __float22half2_rn(hi);
        *(uint2*)(agg3 + off) = cv.u;
    }
}

// ---------------------------------------------------------------------------
// agg GEMMs, split-K, register-tiled, double-buffered, fp16 A.
// ---------------------------------------------------------------------------
__global__ __launch_bounds__(128) void gemm_agg_k(
    const __half* __restrict__ agg1, const __half* __restrict__ agg2,
    const __half* __restrict__ agg3,
    const float* __restrict__ W1, const float* __restrict__ W2,
    const float* __restrict__ W3, float* __restrict__ part) {
    __shared__ __align__(16) float As_t[2][16][132];
    __shared__ __align__(16) float Bs[2][16][32];
    int bx = blockIdx.x;
    int m0 = blockIdx.y * 128;
    int kz = blockIdx.z;
    const __half* A; const float* B; int ldb, coff, BN;
    if (bx == 0)      { A = agg1; B = W1; ldb = 32; coff = 0;  BN = 32; }
    else if (bx == 1) { A = agg2; B = W2; ldb = 16; coff = 32; BN = 16; }
    else              { A = agg3; B = W3; ldb = 16; coff = 48; BN = 16; }
    int t = threadIdx.x;
    int ty = t >> 3, tx = t & 7;
    float acc[8][4];
#pragma unroll
    for (int r = 0; r < 8; r++)
#pragma unroll
        for (int c = 0; c < 4; c++) acc[r][c] = 0.0f;
    int kbase = kz * (1024 / KSPLIT);
    const int NIT = (1024 / KSPLIT) / 16;   // 8

    int arow = t >> 2;
    int akq = (t & 3) << 2;
    int nf = BN >> 2;
    bool bload = t < 16 * nf;
    int brow = bload ? (t / nf) : 0;
    int bcq = bload ? ((t % nf) << 2) : 0;

    float4 av[4]; float4 bv;
    {
        int k0 = kbase;
#pragma unroll
        for (int j = 0; j < 4; j++) {
            uint2 raw = *(const uint2*)(A + (size_t)(m0 + j * 32 + arow) * 1024 + k0 + akq);
            float2 lo = __half22float2(*(__half2*)&raw.x);
            float2 hi = __half22float2(*(__half2*)&raw.y);
            av[j] = make_float4(lo.x, lo.y, hi.x, hi.y);
        }
        if (bload)
            bv = *(const float4*)(B + (size_t)(k0 + brow) * ldb + bcq);
#pragma unroll
        for (int j = 0; j < 4; j++) {
            int row = j * 32 + arow;
            As_t[0][akq + 0][row] = av[j].x;
            As_t[0][akq + 1][row] = av[j].y;
            As_t[0][akq + 2][row] = av[j].z;
            As_t[0][akq + 3][row] = av[j].w;
        }
        if (bload) *(float4*)&Bs[0][brow][bcq] = bv;
    }
    __syncthreads();
    int cur = 0;

    for (int iter = 0; iter < NIT; iter++) {
        bool has_next = (iter + 1) < NIT;
        if (has_next) {
            int k0 = kbase + (iter + 1) * 16;
#pragma unroll
            for (int j = 0; j < 4; j++) {
                uint2 raw = *(const uint2*)(A + (size_t)(m0 + j * 32 + arow) * 1024 + k0 + akq);
                float2 lo = __half22float2(*(__half2*)&raw.x);
                float2 hi = __half22float2(*(__half2*)&raw.y);
                av[j] = make_float4(lo.x, lo.y, hi.x, hi.y);
            }
            if (bload)
                bv = *(const float4*)(B + (size_t)(k0 + brow) * ldb + bcq);
        }
        if (BN == 32) {
#pragma unroll
            for (int kk = 0; kk < 16; kk++) {
                float4 alo = *(const float4*)&As_t[cur][kk][ty * 8];
                float4 ahi = *(const float4*)&As_t[cur][kk][ty * 8 + 4];
                float4 b = *(const float4*)&Bs[cur][kk][tx * 4];
                float a[8] = {alo.x, alo.y, alo.z, alo.w,
                              ahi.x, ahi.y, ahi.z, ahi.w};
#pragma unroll
                for (int r = 0; r < 8; r++) {
                    acc[r][0] += a[r] * b.x;
                    acc[r][1] += a[r] * b.y;
                    acc[r][2] += a[r] * b.z;
                    acc[r][3] += a[r] * b.w;
                }
            }
        } else {
#pragma unroll
            for (int kk = 0; kk < 16; kk++) {
                float4 alo = *(const float4*)&As_t[cur][kk][ty * 8];
                float4 ahi = *(const float4*)&As_t[cur][kk][ty * 8 + 4];
                float2 b = *(const float2*)&Bs[cur][kk][tx * 2];
                float a[8] = {alo.x, alo.y, alo.z, alo.w,
                              ahi.x, ahi.y, ahi.z, ahi.w};
#pragma unroll
                for (int r = 0; r < 8; r++) {
                    acc[r][0] += a[r] * b.x;
                    acc[r][1] += a[r] * b.y;
                }
            }
        }
        if (has_next) {
            int nxt = cur ^ 1;
#pragma unroll
            for (int j = 0; j < 4; j++) {
                int row = j * 32 + arow;
                As_t[nxt][akq + 0][row] = av[j].x;
                As_t[nxt][akq + 1][row] = av[j].y;
                As_t[nxt][akq + 2][row] = av[j].z;
                As_t[nxt][akq + 3][row] = av[j].w;
            }
            if (bload) *(float4*)&Bs[nxt][brow][bcq] = bv;
            __syncthreads();
            cur = nxt;
        }
    }
    float* P = part + (size_t)kz * (N_NODES * 64);
    if (BN == 32) {
#pragma unroll
        for (int r = 0; r < 8; r++) {
            size_t m = (size_t)(m0 + ty * 8 + r);
            *(float4*)&P[m * 64 + coff + tx * 4] =
                make_float4(acc[r][0], acc[r][1], acc[r][2], acc[r][3]);
        }
    } else {
#pragma unroll
        for (int r = 0; r < 8; r++) {
            size_t m = (size_t)(m0 + ty * 8 + r);
            *(float2*)&P[m * 64 + coff + tx * 2] = make_float2(acc[r][0], acc[r][1]);
        }
    }
}

// ---------------------------------------------------------------------------
// reduce_k: cat = sum of KSPLIT split-K partials; emit per-block cat stats.
// ---------------------------------------------------------------------------
__global__ __launch_bounds__(256) void reduce_k(
    const float* __restrict__ part, float* __restrict__ cat,
    float* __restrict__ stats_c) {
    __shared__ float cs[64], cq[64];
    int by = blockIdx.x;
    int t = threadIdx.x;
    if (t < 64) { cs[t] = 0.0f; cq[t] = 0.0f; }
    __syncthreads();
    int r0 = (t >> 4) * 4;
    int c = (t & 15) * 4;
    float s[4] = {0, 0, 0, 0}, q[4] = {0, 0, 0, 0};
#pragma unroll
    for (int j = 0; j < 4; j++) {
        size_t off = ((size_t)(by * 64 + r0 + j)) * 64 + c;
        float4 v = make_float4(0.f, 0.f, 0.f, 0.f);
#pragma unroll
        for (int p = 0; p < KSPLIT; p++) {
            float4 u = *(const float4*)(part + (size_t)p * (N_NODES * 64) + off);
            v.x += u.x; v.y += u.y; v.z += u.z; v.w += u.w;
        }
        *(float4*)(cat + off) = v;
        s[0] += v.x; q[0] += v.x * v.x;
        s[1] += v.y; q[1] += v.y * v.y;
        s[2] += v.z; q[2] += v.z * v.z;
        s[3] += v.w; q[3] += v.w * v.w;
    }
#pragma unroll
    for (int j = 0; j < 4; j++) {
        atomicAdd(&cs[c + j], s[j]);
        atomicAdd(&cq[c + j], q[j]);
    }
    __syncthreads();
    if (t < 64) {
        stats_c[by * 128 + t] = cs[t];
        stats_c[by * 128 + 64 + t] = cq[t];
    }
}

// ---------------------------------------------------------------------------
// Output GEMM: out += lrelu(bn_out(cat)) @ out_W   [4096,64]x[64,256]
// ---------------------------------------------------------------------------
__global__ __launch_bounds__(256) void gemm_out_k(
    const float* __restrict__ cat, const float* __restrict__ stats_c,
    const float* __restrict__ out_g, const float* __restrict__ out_b,
    const float* __restrict__ outW, float* __restrict__ out) {
    __shared__ float s_sc[64], s_bi[64];
    __shared__ __align__(16) float As[16][65];
    __shared__ __align__(16) float Bs[16][64];
    int t = threadIdx.x;
    bn_fold(stats_c, 64, 64, out_g, out_b, s_sc, s_bi, t, 256);
    int n0 = blockIdx.x * 64;
    int m0 = blockIdx.y * 64;
    int tx = t & 15, ty = t >> 4;
    int lam = t >> 2, lak = (t & 3) << 2;
    int lbk = t >> 4, lbn = (t & 15) << 2;
    float acc[4][4];
#pragma unroll
    for (int r = 0; r < 4; r++)
#pragma unroll
        for (int cc = 0; cc < 4; cc++) acc[r][cc] = 0.0f;
    __syncthreads();

    for (int k0 = 0; k0 < 64; k0 += 16) {
        float4 av = *(const float4*)(cat + (size_t)(m0 + lam) * 64 + k0 + lak);
        float v;
        v = av.x * s_sc[k0 + lak + 0] + s_bi[k0 + lak + 0]; av.x = v > 0.0f ? v : 0.1f * v;
        v = av.y * s_sc[k0 + lak + 1] + s_bi[k0 + lak + 1]; av.y = v > 0.0f ? v : 0.1f * v;
        v = av.z * s_sc[k0 + lak + 2] + s_bi[k0 + lak + 2]; av.z = v > 0.0f ? v : 0.1f * v;
        v = av.w * s_sc[k0 + lak + 3] + s_bi[k0 + lak + 3]; av.w = v > 0.0f ? v : 0.1f * v;
        As[lak + 0][lam] = av.x;
        As[lak + 1][lam] = av.y;
        As[lak + 2][lam] = av.z;
        As[lak + 3][lam] = av.w;
        float4 bv = *(const float4*)(outW + (size_t)(k0 + lbk) * 256 + n0 + lbn);
        *(float4*)&Bs[lbk][lbn] = bv;
        __syncthreads();
#pragma unroll
        for (int kk = 0; kk < 16; kk++) {
            float a0 = As[kk][ty * 4 + 0];
            float a1 = As[kk][ty * 4 + 1];
            float a2 = As[kk][ty * 4 + 2];
            float a3 = As[kk][ty * 4 + 3];
            float4 b = *(const float4*)&Bs[kk][tx * 4];
            acc[0][0] += a0 * b.x; acc[0][1] += a0 * b.y; acc[0][2] += a0 * b.z; acc[0][3] += a0 * b.w;
            acc[1][0] += a1 * b.x; acc[1][1] += a1 * b.y; acc[1][2] += a1 * b.z; acc[1][3] += a1 * b.w;
            acc[2][0] += a2 * b.x; acc[2][1] += a2 * b.y; acc[2][2] += a2 * b.z; acc[2][3] += a2 * b.w;
            acc[3][0] += a3 * b.x; acc[3][1] += a3 * b.y; acc[3][2] += a3 * b.z; acc[3][3] += a3 * b.w;
        }
        __syncthreads();
    }
#pragma unroll
    for (int r = 0; r < 4; r++) {
        size_t m = m0 + ty * 4 + r;
#pragma unroll
        for (int cc = 0; cc < 4; cc++) {
            float* p = out + m * 256 + n0 + tx * 4 + cc;
            *p += acc[r][cc];
        }
    }
}

// ---------------------------------------------------------------------------
// Launch
// ---------------------------------------------------------------------------
extern "C" void kernel_launch(void* const* d_in, const int* in_sizes, int n_in,
                              void* d_out, int out_size) {
    const float* x    = (const float*)d_in[0];
    const float* pos  = (const float*)d_in[1];
    const float* ori  = (const float*)d_in[2];
    const int*   seq  = (const int*)d_in[3];
    // d_in[4] = batch (implied by graph)
    const int* src1 = (const int*)d_in[5];
    const int* dst1 = (const int*)d_in[6];
    // src2/dst2, src3/dst3 unused: nested-radius property recovers them
    const float* id_g = (const float*)d_in[11];
    const float* id_b = (const float*)d_in[12];
    const float* id_W = (const float*)d_in[13];
    const float* in_g = (const float*)d_in[14];
    const float* in_b = (const float*)d_in[15];
    const float* in_W = (const float*)d_in[16];
    const float* mid_g = (const float*)d_in[17];
    const float* mid_b = (const float*)d_in[18];
    const float* Ws1 = (const float*)d_in[19];
    const float* bs1 = (const float*)d_in[20];
    const float* W1  = (const float*)d_in[21];
    const float* Ws2 = (const float*)d_in[22];
    const float* bs2 = (const float*)d_in[23];
    const float* W2  = (const float*)d_in[24];
    const float* Ws3 = (const float*)d_in[25];
    const float* bs3 = (const float*)d_in[26];
    const float* W3  = (const float*)d_in[27];
    const float* out_g = (const float*)d_in[28];
    const float* out_b = (const float*)d_in[29];
    const float* out_W = (const float*)d_in[30];
    float* out = (float*)d_out;

    int E1 = in_sizes[5];

    float *h0, *cat, *part, *stats, *sb;
    __half *agg1, *agg2, *agg3;
    int* ro;
    cudaGetSymbolAddress((void**)&h0, g_h0);
    cudaGetSymbolAddress((void**)&agg1, g_agg1);
    cudaGetSymbolAddress((void**)&agg2, g_agg2);
    cudaGetSymbolAddress((void**)&agg3, g_agg3);
    cudaGetSymbolAddress((void**)&cat, g_cat);
    cudaGetSymbolAddress((void**)&part, g_part);
    cudaGetSymbolAddress((void**)&stats, g_stats);
    cudaGetSymbolAddress((void**)&sb, g_sb);
    cudaGetSymbolAddress((void**)&ro, g_ro);
    float* stats_x = stats;              // 16 slots * 256
    float* stats_h = stats + 4096;       // 64 slots * 128
    float* stats_c = stats + 12288;      // 64 slots * 128

    // 1. x column stats + branch-1 CSR
    prep_k<<<33, 256>>>(x, dst1, E1, stats_x, ro);
    // 2. identity GEMM -> out, input GEMM -> h0 (+ h0 stats)
    gemm_x_k<<<dim3(5, 64), 256>>>(x, stats_x, id_g, id_b, id_W,
                                   in_g, in_b, in_W, out, h0, stats_h);
    // 3. fold mid-BN once
    fold_bn_k<<<1, 64>>>(stats_h, mid_g, mid_b, sb);
    // 4. fused 3-branch edge aggregation (pre-folded BN, smem weights)
    edge_all_k<<<N_NODES, 256>>>(h0, pos, ori, seq, src1, ro,
                                 Ws1, bs1, Ws2, bs2, Ws3, bs3,
                                 sb, agg1, agg2, agg3);
    // 5. agg GEMMs, split-K, register-tiled, double-buffered, fp16 A
    gemm_agg_k<<<dim3(3, 32, KSPLIT), 128>>>(agg1, agg2, agg3, W1, W2, W3, part);
    // 6. reduce partials -> cat (+ cat stats)
    reduce_k<<<64, 256>>>(part, cat, stats_c);
    // 7. output GEMM, accumulate onto identity
    gemm_out_k<<<dim3(4, 64), 256>>>(cat, stats_c, out_g, out_b, out_W, out);
}

// round 11
// speedup vs baseline: 1.1205x; 1.1205x over previous
#include <cuda_runtime.h>
#include <cuda_fp16.h>

// ---------------------------------------------------------------------------
// Problem constants
// ---------------------------------------------------------------------------
#define N_NODES 4096
#define AGGW    1024     // K(16) * WIDTH(64)
#define KSPLIT  4

// ---------------------------------------------------------------------------
// Packed f32x2 helpers (sm_103a FFMA2 path)
// ---------------------------------------------------------------------------
__device__ __forceinline__ unsigned long long ffma2(unsigned long long a,
                                                    unsigned long long b,
                                                    unsigned long long c) {
    unsigned long long d;
    asm("fma.rn.f32x2 %0, %1, %2, %3;" : "=l"(d) : "l"(a), "l"(b), "l"(c));
    return d;
}
__device__ __forceinline__ unsigned long long fpack2(float lo, float hi) {
    unsigned long long r;
    asm("mov.b64 %0, {%1, %2};" : "=l"(r) : "f"(lo), "f"(hi));
    return r;
}
__device__ __forceinline__ float2 funpack2(unsigned long long v) {
    float lo, hi;
    asm("mov.b64 {%0, %1}, %2;" : "=f"(lo), "=f"(hi) : "l"(v));
    return make_float2(lo, hi);
}
__device__ __forceinline__ unsigned smem_u32(const void* p) {
    return (unsigned)__cvta_generic_to_shared(p);
}

// ---------------------------------------------------------------------------
// Scratch (device globals -- no allocation allowed). 16B-aligned for float4.
// ---------------------------------------------------------------------------
__device__ __align__(16) float g_h0[N_NODES * 64];
__device__ __align__(16) __half g_agg1[N_NODES * AGGW];
__device__ __align__(16) __half g_agg2[N_NODES * AGGW];
__device__ __align__(16) __half g_agg3[N_NODES * AGGW];
__device__ __align__(16) float g_cat[N_NODES * 64];
__device__ __align__(16) float g_part[KSPLIT * N_NODES * 64];   // split-K partials
// partial column stats: x: 16 slots * 256 = 4096
//                       h0: 64 slots * 128 = 8192 at offset 4096
//                       cat: 64 slots * 128 = 8192 at offset 12288
__device__ float g_stats[20480];
__device__ float g_sb[128];          // mid-BN folded scale[0:64) / bias[64:128)
__device__ int   g_ro[N_NODES + 1];

// ---------------------------------------------------------------------------
// BN fold: reduce nslots partial (sum, sq) -> per-channel scale/bias in smem
// ---------------------------------------------------------------------------
__device__ __forceinline__ void bn_fold(const float* __restrict__ stats, int C,
                                        int nslots,
                                        const float* __restrict__ g,
                                        const float* __restrict__ b,
                                        float* s_sc, float* s_bi,
                                        int t, int nthreads) {
    for (int c = t; c < C; c += nthreads) {
        float s = 0.0f, q = 0.0f;
        for (int bk = 0; bk < nslots; bk++) {
            s += stats[bk * 2 * C + c];
            q += stats[bk * 2 * C + C + c];
        }
        float m = s * (1.0f / N_NODES);
        float v = q * (1.0f / N_NODES) - m * m;
        float rs = rsqrtf(v + 1e-5f);
        float sc = rs * g[c];
        s_sc[c] = sc;
        s_bi[c] = b[c] - m * sc;
    }
}

// ---------------------------------------------------------------------------
// fold_bn_k: one block, folds the 64-slot h0 stats into g_sb once
// ---------------------------------------------------------------------------
__global__ void fold_bn_k(const float* __restrict__ stats,
                          const float* __restrict__ g,
                          const float* __restrict__ b,
                          float* __restrict__ sb) {
    int c = threadIdx.x;   // 64 threads
    float s = 0.0f, q = 0.0f;
    for (int bk = 0; bk < 64; bk++) {
        s += stats[bk * 128 + c];
        q += stats[bk * 128 + 64 + c];
    }
    float m = s * (1.0f / N_NODES);
    float v = q * (1.0f / N_NODES) - m * m;
    float rs = rsqrtf(v + 1e-5f);
    float sc = rs * g[c];
    sb[c] = sc;
    sb[64 + c] = b[c] - m * sc;
}

// ---------------------------------------------------------------------------
// prep: blocks 0..15 -> partial column stats of x (C=128)
//       blocks 16..32 -> CSR row offsets for branch-1 dst (binary search)
// ---------------------------------------------------------------------------
__global__ void prep_k(const float* __restrict__ x, const int* __restrict__ dst,
                       int E, float* __restrict__ stats_x, int* __restrict__ ro) {
    int bx = blockIdx.x;
    if (bx < 16) {
        int c = threadIdx.x;
        if (c < 128) {
            int r0 = bx * 256;
            float s = 0.0f, s2 = 0.0f;
            for (int r = r0; r < r0 + 256; r++) {
                float v = x[(size_t)r * 128 + c];
                s += v;
                s2 += v * v;
            }
            stats_x[bx * 256 + c] = s;
            stats_x[bx * 256 + 128 + c] = s2;
        }
    } else {
        int t = (bx - 16) * 256 + threadIdx.x;
        if (t > N_NODES) return;
        if (t == N_NODES) { ro[t] = E; return; }
        int lo = 0, hi = E;
        while (lo < hi) {
            int mid = (lo + hi) >> 1;
            if (dst[mid] < t) lo = mid + 1; else hi = mid;
        }
        ro[t] = lo;
    }
}

// ---------------------------------------------------------------------------
// gemm_x: merged identity + input GEMMs on A = x [4096,128].
// ---------------------------------------------------------------------------
__global__ __launch_bounds__(256) void gemm_x_k(
    const float* __restrict__ x, const float* __restrict__ stats_x,
    const float* __restrict__ id_g, const float* __restrict__ id_b,
    const float* __restrict__ idW,
    const float* __restrict__ in_g, const float* __restrict__ in_b,
    const float* __restrict__ inW,
    float* __restrict__ out, float* __restrict__ h0,
    float* __restrict__ stats_h) {
    __shared__ float s_sc[128], s_bi[128];
    __shared__ __align__(16) float As[16][65];
    __shared__ __align__(16) float Bs[16][64];
    __shared__ float hs[64], hq[64];
    int t = threadIdx.x;
    int bx = blockIdx.x;
    bool idp = bx < 4;
    bn_fold(stats_x, 128, 16, idp ? id_g : in_g, idp ? id_b : in_b, s_sc, s_bi, t, 256);

    const float* B = idp ? idW : inW;
    int Nd = idp ? 256 : 64;
    int n0 = idp ? bx * 64 : 0;
    float* C = idp ? out : h0;
    int m0 = blockIdx.y * 64;
    int tx = t & 15, ty = t >> 4;
    int lam = t >> 2, lak = (t & 3) << 2;
    int lbk = t >> 4, lbn = (t & 15) << 2;
    float acc[4][4];
#pragma unroll
    for (int r = 0; r < 4; r++)
#pragma unroll
        for (int cc = 0; cc < 4; cc++) acc[r][cc] = 0.0f;
    if (t < 64) { hs[t] = 0.0f; hq[t] = 0.0f; }
    __syncthreads();

    for (int k0 = 0; k0 < 128; k0 += 16) {
        float4 av = *(const float4*)(x + (size_t)(m0 + lam) * 128 + k0 + lak);
        float v;
        v = av.x * s_sc[k0 + lak + 0] + s_bi[k0 + lak + 0]; av.x = v > 0.0f ? v : 0.1f * v;
        v = av.y * s_sc[k0 + lak + 1] + s_bi[k0 + lak + 1]; av.y = v > 0.0f ? v : 0.1f * v;
        v = av.z * s_sc[k0 + lak + 2] + s_bi[k0 + lak + 2]; av.z = v > 0.0f ? v : 0.1f * v;
        v = av.w * s_sc[k0 + lak + 3] + s_bi[k0 + lak + 3]; av.w = v > 0.0f ? v : 0.1f * v;
        As[lak + 0][lam] = av.x;
        As[lak + 1][lam] = av.y;
        As[lak + 2][lam] = av.z;
        As[lak + 3][lam] = av.w;
        float4 bv = *(const float4*)(B + (size_t)(k0 + lbk) * Nd + n0 + lbn);
        *(float4*)&Bs[lbk][lbn] = bv;
        __syncthreads();
#pragma unroll
        for (int kk = 0; kk < 16; kk++) {
            float a0 = As[kk][ty * 4 + 0];
            float a1 = As[kk][ty * 4 + 1];
            float a2 = As[kk][ty * 4 + 2];
            float a3 = As[kk][ty * 4 + 3];
            float4 b = *(const float4*)&Bs[kk][tx * 4];
            acc[0][0] += a0 * b.x; acc[0][1] += a0 * b.y; acc[0][2] += a0 * b.z; acc[0][3] += a0 * b.w;
            acc[1][0] += a1 * b.x; acc[1][1] += a1 * b.y; acc[1][2] += a1 * b.z; acc[1][3] += a1 * b.w;
            acc[2][0] += a2 * b.x; acc[2][1] += a2 * b.y; acc[2][2] += a2 * b.z; acc[2][3] += a2 * b.w;
            acc[3][0] += a3 * b.x; acc[3][1] += a3 * b.y; acc[3][2] += a3 * b.z; acc[3][3] += a3 * b.w;
        }
        __syncthreads();
    }
#pragma unroll
    for (int r = 0; r < 4; r++) {
        int m = m0 + ty * 4 + r;
#pragma unroll
        for (int cc = 0; cc < 4; cc++)
            C[(size_t)m * Nd + n0 + tx * 4 + cc] = acc[r][cc];
    }
    if (!idp) {
#pragma unroll
        for (int cc = 0; cc < 4; cc++) {
            float s = acc[0][cc] + acc[1][cc] + acc[2][cc] + acc[3][cc];
            float q = acc[0][cc] * acc[0][cc] + acc[1][cc] * acc[1][cc] +
                      acc[2][cc] * acc[2][cc] + acc[3][cc] * acc[3][cc];
            atomicAdd(&hs[tx * 4 + cc], s);
            atomicAdd(&hq[tx * 4 + cc], q);
        }
        __syncthreads();
        if (t < 64) {
            stats_h[blockIdx.y * 128 + t] = hs[t];
            stats_h[blockIdx.y * 128 + 64 + t] = hq[t];
        }
    }
}

// ---------------------------------------------------------------------------
// Fused edge aggregation for ALL THREE branches in one pass over branch-1 CSR.
// (R10-measured version: pre-folded mid-BN, Ws/bs staged in smem.)
// ---------------------------------------------------------------------------
#define EB 32
__global__ __launch_bounds__(256) void edge_all_k(
    const float* __restrict__ h0, const float* __restrict__ pos,
    const float* __restrict__ ori, const int* __restrict__ seq,
    const int* __restrict__ src, const int* __restrict__ ro,
    const float* __restrict__ Ws1, const float* __restrict__ bs1,
    const float* __restrict__ Ws2, const float* __restrict__ bs2,
    const float* __restrict__ Ws3, const float* __restrict__ bs3,
    const float* __restrict__ sb,
    __half* __restrict__ agg1, __half* __restrict__ agg2,
    __half* __restrict__ agg3) {
    const double R2SQ = 1.8 * 1.8;
    const double R3T  = 0.75 * 1.8;
    const double R3SQ = R3T * R3T;
    __shared__ float s_sc[64], s_bi[64];
    __shared__ float s_W1[5 * 112],  s_b1[5 * 16];
    __shared__ float s_W2[7 * 112],  s_b2[7 * 16];
    __shared__ float s_W3[11 * 112], s_b3[11 * 16];
    __shared__ float s_fri[9];
    __shared__ float s_posi[3];
    __shared__ int   s_seqi;
    __shared__ float s_d[EB];
    __shared__ int   s_in2[EB], s_in3[EB];
    __shared__ float s_feat[EB][6];
    __shared__ int   s_ds[EB], s_src[EB];
    __shared__ __align__(16) unsigned long long s_wp[EB][16][4]; // {w1,w1}{w2,w2}{w3,w3}pad
    __shared__ __align__(16) float s_h[EB][64];

    int i = blockIdx.x;
    int t = threadIdx.x;
    if (t < 128) { if (t < 64) s_sc[t] = sb[t]; else s_bi[t - 64] = sb[t]; }
    for (int j = t; j < 5 * 112; j += 256)  s_W1[j] = Ws1[j];
    for (int j = t; j < 5 * 16; j += 256)   s_b1[j] = bs1[j];
    for (int j = t; j < 7 * 112; j += 256)  s_W2[j] = Ws2[j];
    for (int j = t; j < 7 * 16; j += 256)   s_b2[j] = bs2[j];
    for (int j = t; j < 11 * 112; j += 256) s_W3[j] = Ws3[j];
    for (int j = t; j < 11 * 16; j += 256)  s_b3[j] = bs3[j];
    if (t < 9)  s_fri[t] = ori[i * 9 + t];
    if (t >= 9 && t < 12) s_posi[t - 9] = pos[i * 3 + (t - 9)];
    if (t == 12) s_seqi = seq[i];

    int start = ro[i], end = ro[i + 1];
    unsigned long long A1lo = 0ull, A1hi = 0ull;
    unsigned long long A2lo = 0ull, A2hi = 0ull;
    unsigned long long A3lo = 0ull, A3hi = 0ull;
    int k = t >> 4, c0 = (t & 15) << 2;
    __syncthreads();

    for (int e0 = start; e0 < end; e0 += EB) {
        int ne = min(EB, end - e0);
        // --- Phase A: per-edge geometry (1 thread per edge) ---
        if (t < ne) {
            int js = src[e0 + t];
            s_src[t] = js;
            float dx = __fadd_rn(pos[js * 3 + 0], -s_posi[0]);
            float dy = __fadd_rn(pos[js * 3 + 1], -s_posi[1]);
            float dz = __fadd_rn(pos[js * 3 + 2], -s_posi[2]);
            float d2 = __fadd_rn(__fadd_rn(__fmul_rn(dx, dx), __fmul_rn(dy, dy)),
                                 __fmul_rn(dz, dz));
            double d2d = (double)d2;
            s_in2[t] = (d2d <= R2SQ) ? 1 : 0;
            s_in3[t] = (d2d <= R3SQ) ? 1 : 0;
            float dist = sqrtf(d2);
            s_d[t] = dist;
            float inv = 1.0f / (dist + 1e-9f);
            float ux = dx * inv, uy = dy * inv, uz = dz * inv;
            float f0 = s_fri[0], f1 = s_fri[1], f2 = s_fri[2];
            float f3 = s_fri[3], f4 = s_fri[4], f5 = s_fri[5];
            float f6 = s_fri[6], f7 = s_fri[7], f8 = s_fri[8];
            s_feat[t][0] = f0 * ux + f1 * uy + f2 * uz;
            s_feat[t][1] = f3 * ux + f4 * uy + f5 * uz;
            s_feat[t][2] = f6 * ux + f7 * uy + f8 * uz;
            const float* op = ori + (size_t)js * 9;
            s_feat[t][3] = f0 * op[0] + f1 * op[1] + f2 * op[2];
            s_feat[t][4] = f3 * op[3] + f4 * op[4] + f5 * op[5];
            s_feat[t][5] = f6 * op[6] + f7 * op[7] + f8 * op[8];
            s_ds[t] = seq[js] - s_seqi;
        }
        __syncthreads();
        // --- Phase B1: edge weights per branch (weights from smem) ---
        for (int task = t; task < ne * 16; task += 256) {   // branch 1
            int e = task >> 4, kk = task & 15;
            int d = s_ds[e]; d = max(-2, min(2, d));
            int idx = d + 2;
            const float* wr = s_W1 + idx * 112 + kk;
            float s = s_b1[idx * 16 + kk] + (s_d[e] / 2.7f) * wr[0];
#pragma unroll
            for (int cc = 0; cc < 6; cc++) s += s_feat[e][cc] * wr[(cc + 1) * 16];
            s = s > 0.0f ? s : 0.2f * s;
            s_wp[e][kk][0] = fpack2(s, s);
        }
        for (int task = t; task < ne * 16; task += 256) {   // branch 2
            int e = task >> 4, kk = task & 15;
            float w = 0.0f;
            if (s_in2[e]) {
                int d = s_ds[e]; d = max(-3, min(3, d));
                int idx = d + 3;
                const float* wr = s_W2 + idx * 112 + kk;
                float s = s_b2[idx * 16 + kk] + (s_d[e] / 1.8f) * wr[0];
#pragma unroll
                for (int cc = 0; cc < 6; cc++) s += s_feat[e][cc] * wr[(cc + 1) * 16];
                w = s > 0.0f ? s : 0.2f * s;
            }
            s_wp[e][kk][1] = fpack2(w, w);
        }
        for (int task = t; task < ne * 16; task += 256) {   // branch 3
            int e = task >> 4, kk = task & 15;
            float w = 0.0f;
            if (s_in3[e]) {
                int d = s_ds[e]; d = max(-5, min(5, d));
                int idx = d + 5;
                const float* wr = s_W3 + idx * 112 + kk;
                float s = s_b3[idx * 16 + kk] + (s_d[e] / 1.35f) * wr[0];
#pragma unroll
                for (int cc = 0; cc < 6; cc++) s += s_feat[e][cc] * wr[(cc + 1) * 16];
                w = s > 0.0f ? s : 0.2f * s;
            }
            s_wp[e][kk][2] = fpack2(w, w);
        }
        // --- Phase B2: gather h0 rows with mid-BN + lrelu folded in ---
        for (int task = t; task < ne * 16; task += 256) {
            int e = task >> 4, q = task & 15;
            int cc = q << 2;
            float4 v = *(const float4*)(h0 + (size_t)s_src[e] * 64 + cc);
            float u;
            u = v.x * s_sc[cc + 0] + s_bi[cc + 0]; v.x = u > 0.0f ? u : 0.1f * u;
            u = v.y * s_sc[cc + 1] + s_bi[cc + 1]; v.y = u > 0.0f ? u : 0.1f * u;
            u = v.z * s_sc[cc + 2] + s_bi[cc + 2]; v.z = u > 0.0f ? u : 0.1f * u;
            u = v.w * s_sc[cc + 3] + s_bi[cc + 3]; v.w = u > 0.0f ? u : 0.1f * u;
            *(float4*)&s_h[e][cc] = v;
        }
        __syncthreads();
        // --- Phase C: packed rank-1 accumulate: 3 LDS + 6 FFMA2 per edge ---
        for (int e = 0; e < ne; e++) {
            ulonglong2 h2 = *(const ulonglong2*)&s_h[e][c0];
            ulonglong2 w12 = *(const ulonglong2*)&s_wp[e][k][0];
            unsigned long long w3p = s_wp[e][k][2];
            A1lo = ffma2(w12.x, h2.x, A1lo); A1hi = ffma2(w12.x, h2.y, A1hi);
            A2lo = ffma2(w12.y, h2.x, A2lo); A2hi = ffma2(w12.y, h2.y, A2hi);
            A3lo = ffma2(w3p,  h2.x, A3lo); A3hi = ffma2(w3p,  h2.y, A3hi);
        }
        __syncthreads();
    }
    size_t off = (size_t)i * AGGW + k * 64 + c0;
    {
        float2 lo = funpack2(A1lo), hi = funpack2(A1hi);
        union { __half2 h2[2]; uint2 u; } cv;
        cv.h2[0] = __float22half2_rn(lo);
        cv.h2[1] = __float22half2_rn(hi);
        *(uint2*)(agg1 + off) = cv.u;
    }
    {
        float2 lo = funpack2(A2lo), hi = funpack2(A2hi);
        union { __half2 h2[2]; uint2 u; } cv;
        cv.h2[0] = __float22half2_rn(lo);
        cv.h2[1] = __float22half2_rn(hi);
        *(uint2*)(agg2 + off) = cv.u;
    }
    {
        float2 lo = funpack2(A3lo), hi = funpack2(A3hi);
        union { __half2 h2[2]; uint2 u; } cv;
        cv.h2[0] = __float22half2_rn(lo);
        cv.h2[1] = __float22half2_rn(hi);
        *(uint2*)(agg3 + off) = cv.u;
    }
}

// ---------------------------------------------------------------------------
// agg GEMMs, TENSOR CORE (HMMA m16n8k16), split-K:
//   grid (3 branches, 64 M-tiles, KSPLIT), 128 threads (4 warps x 16 rows).
//   A = agg fp16 [4096,1024]; B = W converted fp32->fp16 at stage time.
//   K staged 64 per iter; ldmatrix x4 (A) / x2.trans (B); f32 accumulators.
// ---------------------------------------------------------------------------
#define A_STRIDE 72   // halves per As row (16B aligned, conflict-light LDSM)
#define B_STRIDE 40   // halves per Bs row
__global__ __launch_bounds__(128) void gemm_agg_k(
    const __half* __restrict__ agg1, const __half* __restrict__ agg2,
    const __half* __restrict__ agg3,
    const float* __restrict__ W1, const float* __restrict__ W2,
    const float* __restrict__ W3, float* __restrict__ part) {
    __shared__ __align__(16) __half As[64 * A_STRIDE];
    __shared__ __align__(16) __half Bsm[64 * B_STRIDE];
    int bx = blockIdx.x;
    int m0 = blockIdx.y * 64;
    int kz = blockIdx.z;
    const __half* A; const float* B; int ldb, coff, BN;
    if (bx == 0)      { A = agg1; B = W1; ldb = 32; coff = 0;  BN = 32; }
    else if (bx == 1) { A = agg2; B = W2; ldb = 16; coff = 32; BN = 16; }
    else              { A = agg3; B = W3; ldb = 16; coff = 48; BN = 16; }
    int t = threadIdx.x;
    int w = t >> 5, lane = t & 31;
    int nt_cnt = BN >> 3;                 // 4 or 2 n-tiles of 8
    float d[4][4];
#pragma unroll
    for (int i = 0; i < 4; i++)
#pragma unroll
        for (int j = 0; j < 4; j++) d[i][j] = 0.0f;
    int kbase = kz * (1024 / KSPLIT);     // 256 per split

    // stage geometry
    int aseg = t & 7;                     // 8 segments x 8 halves = 64 k
    int arow0 = t >> 3;                   // 16 rows per pass, 4 passes
    int nf = ldb >> 2;                    // float4 per B row (8 or 4)
    // ldmatrix lane addressing
    int lrow = lane & 15;
    int lkoff = (lane >> 4) * 8;

    for (int ks = 0; ks < 1024 / KSPLIT; ks += 64) {
        int k0 = kbase + ks;
        __syncthreads();
        // stage A: 64 rows x 64 halves
#pragma unroll
        for (int j = 0; j < 4; j++) {
            int row = j * 16 + arow0;
            uint4 v = *(const uint4*)(A + (size_t)(m0 + row) * 1024 + k0 + aseg * 8);
            *(uint4*)&As[row * A_STRIDE + aseg * 8] = v;
        }
        // stage B: 64 k-rows x BN cols, cvt fp32 -> fp16
        for (int idx = t; idx < 64 * nf; idx += 128) {
            int row = idx / nf, cq = (idx % nf) << 2;
            float4 v = *(const float4*)(B + (size_t)(k0 + row) * ldb + cq);
            __half2 h01 = __floats2half2_rn(v.x, v.y);
            __half2 h23 = __floats2half2_rn(v.z, v.w);
            *(__half2*)&Bsm[row * B_STRIDE + cq] = h01;
            *(__half2*)&Bsm[row * B_STRIDE + cq + 2] = h23;
        }
        __syncthreads();
        // compute: 4 k16 chunks
#pragma unroll
        for (int kk = 0; kk < 4; kk++) {
            unsigned a0, a1, a2, a3;
            unsigned addrA = smem_u32(&As[(w * 16 + lrow) * A_STRIDE + kk * 16 + lkoff]);
            asm volatile("ldmatrix.sync.aligned.m8n8.x4.shared.b16 {%0,%1,%2,%3}, [%4];"
                         : "=r"(a0), "=r"(a1), "=r"(a2), "=r"(a3) : "r"(addrA));
            for (int nt = 0; nt < nt_cnt; nt++) {
                unsigned b0, b1;
                unsigned addrB = smem_u32(&Bsm[(kk * 16 + lrow) * B_STRIDE + nt * 8]);
                asm volatile("ldmatrix.sync.aligned.m8n8.x2.trans.shared.b16 {%0,%1}, [%2];"
                             : "=r"(b0), "=r"(b1) : "r"(addrB));
                asm volatile("mma.sync.aligned.m16n8k16.row.col.f32.f16.f16.f32 "
                             "{%0,%1,%2,%3}, {%4,%5,%6,%7}, {%8,%9}, {%0,%1,%2,%3};"
                             : "+f"(d[nt][0]), "+f"(d[nt][1]), "+f"(d[nt][2]), "+f"(d[nt][3])
                             : "r"(a0), "r"(a1), "r"(a2), "r"(a3), "r"(b0), "r"(b1));
            }
        }
    }
    // writeout: thread holds rows (g, g+8), cols 2q, 2q+1 per n-tile
    float* P = part + (size_t)kz * (N_NODES * 64);
    int g = lane >> 2, q = lane & 3;
    size_t r0 = (size_t)(m0 + w * 16 + g);
    for (int nt = 0; nt < nt_cnt; nt++) {
        int c = coff + nt * 8 + q * 2;
        *(float2*)&P[r0 * 64 + c] = make_float2(d[nt][0], d[nt][1]);
        *(float2*)&P[(r0 + 8) * 64 + c] = make_float2(d[nt][2], d[nt][3]);
    }
}

// ---------------------------------------------------------------------------
// reduce_k: cat = sum of KSPLIT split-K partials; emit per-block cat stats.
// ---------------------------------------------------------------------------
__global__ __launch_bounds__(256) void reduce_k(
    const float* __restrict__ part, float* __restrict__ cat,
    float* __restrict__ stats_c) {
    __shared__ float cs[64], cq[64];
    int by = blockIdx.x;
    int t = threadIdx.x;
    if (t < 64) { cs[t] = 0.0f; cq[t] = 0.0f; }
    __syncthreads();
    int r0 = (t >> 4) * 4;
    int c = (t & 15) * 4;
    float s[4] = {0, 0, 0, 0}, q[4] = {0, 0, 0, 0};
#pragma unroll
    for (int j = 0; j < 4; j++) {
        size_t off = ((size_t)(by * 64 + r0 + j)) * 64 + c;
        float4 v = make_float4(0.f, 0.f, 0.f, 0.f);
#pragma unroll
        for (int p = 0; p < KSPLIT; p++) {
            float4 u = *(const float4*)(part + (size_t)p * (N_NODES * 64) + off);
            v.x += u.x; v.y += u.y; v.z += u.z; v.w += u.w;
        }
        *(float4*)(cat + off) = v;
        s[0] += v.x; q[0] += v.x * v.x;
        s[1] += v.y; q[1] += v.y * v.y;
        s[2] += v.z; q[2] += v.z * v.z;
        s[3] += v.w; q[3] += v.w * v.w;
    }
#pragma unroll
    for (int j = 0; j < 4; j++) {
        atomicAdd(&cs[c + j], s[j]);
        atomicAdd(&cq[c + j], q[j]);
    }
    __syncthreads();
    if (t < 64) {
        stats_c[by * 128 + t] = cs[t];
        stats_c[by * 128 + 64 + t] = cq[t];
    }
}

// ---------------------------------------------------------------------------
// Output GEMM: out += lrelu(bn_out(cat)) @ out_W   [4096,64]x[64,256]
// ---------------------------------------------------------------------------
__global__ __launch_bounds__(256) void gemm_out_k(
    const float* __restrict__ cat, const float* __restrict__ stats_c,
    const float* __restrict__ out_g, const float* __restrict__ out_b,
    const float* __restrict__ outW, float* __restrict__ out) {
    __shared__ float s_sc[64], s_bi[64];
    __shared__ __align__(16) float As[16][65];
    __shared__ __align__(16) float Bs[16][64];
    int t = threadIdx.x;
    bn_fold(stats_c, 64, 64, out_g, out_b, s_sc, s_bi, t, 256);
    int n0 = blockIdx.x * 64;
    int m0 = blockIdx.y * 64;
    int tx = t & 15, ty = t >> 4;
    int lam = t >> 2, lak = (t & 3) << 2;
    int lbk = t >> 4, lbn = (t & 15) << 2;
    float acc[4][4];
#pragma unroll
    for (int r = 0; r < 4; r++)
#pragma unroll
        for (int cc = 0; cc < 4; cc++) acc[r][cc] = 0.0f;
    __syncthreads();

    for (int k0 = 0; k0 < 64; k0 += 16) {
        float4 av = *(const float4*)(cat + (size_t)(m0 + lam) * 64 + k0 + lak);
        float v;
        v = av.x * s_sc[k0 + lak + 0] + s_bi[k0 + lak + 0]; av.x = v > 0.0f ? v : 0.1f * v;
        v = av.y * s_sc[k0 + lak + 1] + s_bi[k0 + lak + 1]; av.y = v > 0.0f ? v : 0.1f * v;
        v = av.z * s_sc[k0 + lak + 2] + s_bi[k0 + lak + 2]; av.z = v > 0.0f ? v : 0.1f * v;
        v = av.w * s_sc[k0 + lak + 3] + s_bi[k0 + lak + 3]; av.w = v > 0.0f ? v : 0.1f * v;
        As[lak + 0][lam] = av.x;
        As[lak + 1][lam] = av.y;
        As[lak + 2][lam] = av.z;
        As[lak + 3][lam] = av.w;
        float4 bv = *(const float4*)(outW + (size_t)(k0 + lbk) * 256 + n0 + lbn);
        *(float4*)&Bs[lbk][lbn] = bv;
        __syncthreads();
#pragma unroll
        for (int kk = 0; kk < 16; kk++) {
            float a0 = As[kk][ty * 4 + 0];
            float a1 = As[kk][ty * 4 + 1];
            float a2 = As[kk][ty * 4 + 2];
            float a3 = As[kk][ty * 4 + 3];
            float4 b = *(const float4*)&Bs[kk][tx * 4];
            acc[0][0] += a0 * b.x; acc[0][1] += a0 * b.y; acc[0][2] += a0 * b.z; acc[0][3] += a0 * b.w;
            acc[1][0] += a1 * b.x; acc[1][1] += a1 * b.y; acc[1][2] += a1 * b.z; acc[1][3] += a1 * b.w;
            acc[2][0] += a2 * b.x; acc[2][1] += a2 * b.y; acc[2][2] += a2 * b.z; acc[2][3] += a2 * b.w;
            acc[3][0] += a3 * b.x; acc[3][1] += a3 * b.y; acc[3][2] += a3 * b.z; acc[3][3] += a3 * b.w;
        }
        __syncthreads();
    }
#pragma unroll
    for (int r = 0; r < 4; r++) {
        size_t m = m0 + ty * 4 + r;
#pragma unroll
        for (int cc = 0; cc < 4; cc++) {
            float* p = out + m * 256 + n0 + tx * 4 + cc;
            *p += acc[r][cc];
        }
    }
}

// ---------------------------------------------------------------------------
// Launch
// ---------------------------------------------------------------------------
extern "C" void kernel_launch(void* const* d_in, const int* in_sizes, int n_in,
                              void* d_out, int out_size) {
    const float* x    = (const float*)d_in[0];
    const float* pos  = (const float*)d_in[1];
    const float* ori  = (const float*)d_in[2];
    const int*   seq  = (const int*)d_in[3];
    // d_in[4] = batch (implied by graph)
    const int* src1 = (const int*)d_in[5];
    const int* dst1 = (const int*)d_in[6];
    // src2/dst2, src3/dst3 unused: nested-radius property recovers them
    const float* id_g = (const float*)d_in[11];
    const float* id_b = (const float*)d_in[12];
    const float* id_W = (const float*)d_in[13];
    const float* in_g = (const float*)d_in[14];
    const float* in_b = (const float*)d_in[15];
    const float* in_W = (const float*)d_in[16];
    const float* mid_g = (const float*)d_in[17];
    const float* mid_b = (const float*)d_in[18];
    const float* Ws1 = (const float*)d_in[19];
    const float* bs1 = (const float*)d_in[20];
    const float* W1  = (const float*)d_in[21];
    const float* Ws2 = (const float*)d_in[22];
    const float* bs2 = (const float*)d_in[23];
    const float* W2  = (const float*)d_in[24];
    const float* Ws3 = (const float*)d_in[25];
    const float* bs3 = (const float*)d_in[26];
    const float* W3  = (const float*)d_in[27];
    const float* out_g = (const float*)d_in[28];
    const float* out_b = (const float*)d_in[29];
    const float* out_W = (const float*)d_in[30];
    float* out = (float*)d_out;

    int E1 = in_sizes[5];

    float *h0, *cat, *part, *stats, *sb;
    __half *agg1, *agg2, *agg3;
    int* ro;
    cudaGetSymbolAddress((void**)&h0, g_h0);
    cudaGetSymbolAddress((void**)&agg1, g_agg1);
    cudaGetSymbolAddress((void**)&agg2, g_agg2);
    cudaGetSymbolAddress((void**)&agg3, g_agg3);
    cudaGetSymbolAddress((void**)&cat, g_cat);
    cudaGetSymbolAddress((void**)&part, g_part);
    cudaGetSymbolAddress((void**)&stats, g_stats);
    cudaGetSymbolAddress((void**)&sb, g_sb);
    cudaGetSymbolAddress((void**)&ro, g_ro);
    float* stats_x = stats;              // 16 slots * 256
    float* stats_h = stats + 4096;       // 64 slots * 128
    float* stats_c = stats + 12288;      // 64 slots * 128

    // 1. x column stats + branch-1 CSR
    prep_k<<<33, 256>>>(x, dst1, E1, stats_x, ro);
    // 2. identity GEMM -> out, input GEMM -> h0 (+ h0 stats)
    gemm_x_k<<<dim3(5, 64), 256>>>(x, stats_x, id_g, id_b, id_W,
                                   in_g, in_b, in_W, out, h0, stats_h);
    // 3. fold mid-BN once
    fold_bn_k<<<1, 64>>>(stats_h, mid_g, mid_b, sb);
    // 4. fused 3-branch edge aggregation (pre-folded BN, smem weights)
    edge_all_k<<<N_NODES, 256>>>(h0, pos, ori, seq, src1, ro,
                                 Ws1, bs1, Ws2, bs2, Ws3, bs3,
                                 sb, agg1, agg2, agg3);
    // 5. agg GEMMs, tensor-core HMMA, split-K (768 blocks)
    gemm_agg_k<<<dim3(3, 64, KSPLIT), 128>>>(agg1, agg2, agg3, W1, W2, W3, part);
    // 6. reduce partials -> cat (+ cat stats)
    reduce_k<<<64, 256>>>(part, cat, stats_c);
    // 7. output GEMM, accumulate onto identity
    gemm_out_k<<<dim3(4, 64), 256>>>(cat, stats_c, out_g, out_b, out_W, out);
}

// round 12
// speedup vs baseline: 1.2220x; 1.0906x over previous
#include <cuda_runtime.h>
#include <cuda_fp16.h>

// ---------------------------------------------------------------------------
// Problem constants
// ---------------------------------------------------------------------------
#define N_NODES 4096
#define AGGW    1024     // K(16) * WIDTH(64)
#define KSPLIT  4

__device__ __forceinline__ unsigned smem_u32(const void* p) {
    return (unsigned)__cvta_generic_to_shared(p);
}

// ---------------------------------------------------------------------------
// Scratch (device globals -- no allocation allowed). 16B-aligned for float4.
// ---------------------------------------------------------------------------
__device__ __align__(16) float g_h0[N_NODES * 64];
__device__ __align__(16) __half g_agg1[N_NODES * AGGW];
__device__ __align__(16) __half g_agg2[N_NODES * AGGW];
__device__ __align__(16) __half g_agg3[N_NODES * AGGW];
__device__ __align__(16) float g_cat[N_NODES * 64];
__device__ __align__(16) float g_part[KSPLIT * N_NODES * 64];   // split-K partials
// partial column stats: x: 16 slots * 256 = 4096
//                       h0: 64 slots * 128 = 8192 at offset 4096
//                       cat: 64 slots * 128 = 8192 at offset 12288
__device__ float g_stats[20480];
__device__ float g_sb[128];          // mid-BN folded scale[0:64) / bias[64:128)
__device__ int   g_ro[N_NODES + 1];

// ---------------------------------------------------------------------------
// BN fold: reduce nslots partial (sum, sq) -> per-channel scale/bias in smem
// ---------------------------------------------------------------------------
__device__ __forceinline__ void bn_fold(const float* __restrict__ stats, int C,
                                        int nslots,
                                        const float* __restrict__ g,
                                        const float* __restrict__ b,
                                        float* s_sc, float* s_bi,
                                        int t, int nthreads) {
    for (int c = t; c < C; c += nthreads) {
        float s = 0.0f, q = 0.0f;
        for (int bk = 0; bk < nslots; bk++) {
            s += stats[bk * 2 * C + c];
            q += stats[bk * 2 * C + C + c];
        }
        float m = s * (1.0f / N_NODES);
        float v = q * (1.0f / N_NODES) - m * m;
        float rs = rsqrtf(v + 1e-5f);
        float sc = rs * g[c];
        s_sc[c] = sc;
        s_bi[c] = b[c] - m * sc;
    }
}

// ---------------------------------------------------------------------------
// fold_bn_k: one block, folds the 64-slot h0 stats into g_sb once
// ---------------------------------------------------------------------------
__global__ void fold_bn_k(const float* __restrict__ stats,
                          const float* __restrict__ g,
                          const float* __restrict__ b,
                          float* __restrict__ sb) {
    int c = threadIdx.x;   // 64 threads
    float s = 0.0f, q = 0.0f;
    for (int bk = 0; bk < 64; bk++) {
        s += stats[bk * 128 + c];
        q += stats[bk * 128 + 64 + c];
    }
    float m = s * (1.0f / N_NODES);
    float v = q * (1.0f / N_NODES) - m * m;
    float rs = rsqrtf(v + 1e-5f);
    float sc = rs * g[c];
    sb[c] = sc;
    sb[64 + c] = b[c] - m * sc;
}

// ---------------------------------------------------------------------------
// prep: blocks 0..15 -> partial column stats of x (C=128)
//       blocks 16..32 -> CSR row offsets for branch-1 dst (binary search)
// ---------------------------------------------------------------------------
__global__ void prep_k(const float* __restrict__ x, const int* __restrict__ dst,
                       int E, float* __restrict__ stats_x, int* __restrict__ ro) {
    int bx = blockIdx.x;
    if (bx < 16) {
        int c = threadIdx.x;
        if (c < 128) {
            int r0 = bx * 256;
            float s = 0.0f, s2 = 0.0f;
            for (int r = r0; r < r0 + 256; r++) {
                float v = x[(size_t)r * 128 + c];
                s += v;
                s2 += v * v;
            }
            stats_x[bx * 256 + c] = s;
            stats_x[bx * 256 + 128 + c] = s2;
        }
    } else {
        int t = (bx - 16) * 256 + threadIdx.x;
        if (t > N_NODES) return;
        if (t == N_NODES) { ro[t] = E; return; }
        int lo = 0, hi = E;
        while (lo < hi) {
            int mid = (lo + hi) >> 1;
            if (dst[mid] < t) lo = mid + 1; else hi = mid;
        }
        ro[t] = lo;
    }
}

// ---------------------------------------------------------------------------
// gemm_x: merged identity + input GEMMs on A = x [4096,128].
// ---------------------------------------------------------------------------
__global__ __launch_bounds__(256) void gemm_x_k(
    const float* __restrict__ x, const float* __restrict__ stats_x,
    const float* __restrict__ id_g, const float* __restrict__ id_b,
    const float* __restrict__ idW,
    const float* __restrict__ in_g, const float* __restrict__ in_b,
    const float* __restrict__ inW,
    float* __restrict__ out, float* __restrict__ h0,
    float* __restrict__ stats_h) {
    __shared__ float s_sc[128], s_bi[128];
    __shared__ __align__(16) float As[16][65];
    __shared__ __align__(16) float Bs[16][64];
    __shared__ float hs[64], hq[64];
    int t = threadIdx.x;
    int bx = blockIdx.x;
    bool idp = bx < 4;
    bn_fold(stats_x, 128, 16, idp ? id_g : in_g, idp ? id_b : in_b, s_sc, s_bi, t, 256);

    const float* B = idp ? idW : inW;
    int Nd = idp ? 256 : 64;
    int n0 = idp ? bx * 64 : 0;
    float* C = idp ? out : h0;
    int m0 = blockIdx.y * 64;
    int tx = t & 15, ty = t >> 4;
    int lam = t >> 2, lak = (t & 3) << 2;
    int lbk = t >> 4, lbn = (t & 15) << 2;
    float acc[4][4];
#pragma unroll
    for (int r = 0; r < 4; r++)
#pragma unroll
        for (int cc = 0; cc < 4; cc++) acc[r][cc] = 0.0f;
    if (t < 64) { hs[t] = 0.0f; hq[t] = 0.0f; }
    __syncthreads();

    for (int k0 = 0; k0 < 128; k0 += 16) {
        float4 av = *(const float4*)(x + (size_t)(m0 + lam) * 128 + k0 + lak);
        float v;
        v = av.x * s_sc[k0 + lak + 0] + s_bi[k0 + lak + 0]; av.x = v > 0.0f ? v : 0.1f * v;
        v = av.y * s_sc[k0 + lak + 1] + s_bi[k0 + lak + 1]; av.y = v > 0.0f ? v : 0.1f * v;
        v = av.z * s_sc[k0 + lak + 2] + s_bi[k0 + lak + 2]; av.z = v > 0.0f ? v : 0.1f * v;
        v = av.w * s_sc[k0 + lak + 3] + s_bi[k0 + lak + 3]; av.w = v > 0.0f ? v : 0.1f * v;
        As[lak + 0][lam] = av.x;
        As[lak + 1][lam] = av.y;
        As[lak + 2][lam] = av.z;
        As[lak + 3][lam] = av.w;
        float4 bv = *(const float4*)(B + (size_t)(k0 + lbk) * Nd + n0 + lbn);
        *(float4*)&Bs[lbk][lbn] = bv;
        __syncthreads();
#pragma unroll
        for (int kk = 0; kk < 16; kk++) {
            float a0 = As[kk][ty * 4 + 0];
            float a1 = As[kk][ty * 4 + 1];
            float a2 = As[kk][ty * 4 + 2];
            float a3 = As[kk][ty * 4 + 3];
            float4 b = *(const float4*)&Bs[kk][tx * 4];
            acc[0][0] += a0 * b.x; acc[0][1] += a0 * b.y; acc[0][2] += a0 * b.z; acc[0][3] += a0 * b.w;
            acc[1][0] += a1 * b.x; acc[1][1] += a1 * b.y; acc[1][2] += a1 * b.z; acc[1][3] += a1 * b.w;
            acc[2][0] += a2 * b.x; acc[2][1] += a2 * b.y; acc[2][2] += a2 * b.z; acc[2][3] += a2 * b.w;
            acc[3][0] += a3 * b.x; acc[3][1] += a3 * b.y; acc[3][2] += a3 * b.z; acc[3][3] += a3 * b.w;
        }
        __syncthreads();
    }
#pragma unroll
    for (int r = 0; r < 4; r++) {
        int m = m0 + ty * 4 + r;
#pragma unroll
        for (int cc = 0; cc < 4; cc++)
            C[(size_t)m * Nd + n0 + tx * 4 + cc] = acc[r][cc];
    }
    if (!idp) {
#pragma unroll
        for (int cc = 0; cc < 4; cc++) {
            float s = acc[0][cc] + acc[1][cc] + acc[2][cc] + acc[3][cc];
            float q = acc[0][cc] * acc[0][cc] + acc[1][cc] * acc[1][cc] +
                      acc[2][cc] * acc[2][cc] + acc[3][cc] * acc[3][cc];
            atomicAdd(&hs[tx * 4 + cc], s);
            atomicAdd(&hq[tx * 4 + cc], q);
        }
        __syncthreads();
        if (t < 64) {
            stats_h[blockIdx.y * 128 + t] = hs[t];
            stats_h[blockIdx.y * 128 + 64 + t] = hq[t];
        }
    }
}

// ---------------------------------------------------------------------------
// Fused edge aggregation, TENSOR-CORE Phase C:
//   per node/branch: agg(16x64) += W(16xE) * H(Ex64) via mma.m16n8k16.
//   w, h stored fp16 in smem; warp w owns cols [w*8, w*8+8); f32 accum.
// ---------------------------------------------------------------------------
#define EB 32
#define WST 24    // s_wh row stride in halves (48B, LDSM conflict-free)
#define HST 72    // s_h row stride in halves (144B, LDSM conflict-free)
__global__ __launch_bounds__(256) void edge_all_k(
    const float* __restrict__ h0, const float* __restrict__ pos,
    const float* __restrict__ ori, const int* __restrict__ seq,
    const int* __restrict__ src, const int* __restrict__ ro,
    const float* __restrict__ Ws1, const float* __restrict__ bs1,
    const float* __restrict__ Ws2, const float* __restrict__ bs2,
    const float* __restrict__ Ws3, const float* __restrict__ bs3,
    const float* __restrict__ sb,
    __half* __restrict__ agg1, __half* __restrict__ agg2,
    __half* __restrict__ agg3) {
    const double R2SQ = 1.8 * 1.8;
    const double R3T  = 0.75 * 1.8;
    const double R3SQ = R3T * R3T;
    __shared__ float s_sc[64], s_bi[64];
    __shared__ float s_W1[5 * 112],  s_b1[5 * 16];
    __shared__ float s_W2[7 * 112],  s_b2[7 * 16];
    __shared__ float s_W3[11 * 112], s_b3[11 * 16];
    __shared__ float s_fri[9];
    __shared__ float s_posi[3];
    __shared__ int   s_seqi;
    __shared__ float s_d[EB];
    __shared__ int   s_in2[EB], s_in3[EB];
    __shared__ float s_feat[EB][6];
    __shared__ int   s_ds[EB], s_src[EB];
    __shared__ __align__(16) __half s_wh[3][EB][WST];   // w per branch, [edge][k]
    __shared__ __align__(16) __half s_h[EB][HST];       // h fp16 [edge][c]

    int i = blockIdx.x;
    int t = threadIdx.x;
    if (t < 128) { if (t < 64) s_sc[t] = sb[t]; else s_bi[t - 64] = sb[t]; }
    for (int j = t; j < 5 * 112; j += 256)  s_W1[j] = Ws1[j];
    for (int j = t; j < 5 * 16; j += 256)   s_b1[j] = bs1[j];
    for (int j = t; j < 7 * 112; j += 256)  s_W2[j] = Ws2[j];
    for (int j = t; j < 7 * 16; j += 256)   s_b2[j] = bs2[j];
    for (int j = t; j < 11 * 112; j += 256) s_W3[j] = Ws3[j];
    for (int j = t; j < 11 * 16; j += 256)  s_b3[j] = bs3[j];
    if (t < 9)  s_fri[t] = ori[i * 9 + t];
    if (t >= 9 && t < 12) s_posi[t - 9] = pos[i * 3 + (t - 9)];
    if (t == 12) s_seqi = seq[i];

    int start = ro[i], end = ro[i + 1];
    int w = t >> 5, lane = t & 31;
    // ldmatrix addressing
    int aerow = ((lane >> 4) & 1) * 8 + (lane & 7);   // A (.x4.trans): edge row
    int amcol = ((lane >> 3) & 1) * 8;                // A: m col-group (halves)
    int bero = lane & 15;                             // B (.x2.trans): edge row
    float d1[4], d2[4], d3[4];
#pragma unroll
    for (int j = 0; j < 4; j++) { d1[j] = 0.0f; d2[j] = 0.0f; d3[j] = 0.0f; }
    __syncthreads();

    for (int e0 = start; e0 < end; e0 += EB) {
        int ne = min(EB, end - e0);
        // --- Phase A: per-edge geometry (1 thread per edge) ---
        if (t < ne) {
            int js = src[e0 + t];
            s_src[t] = js;
            float dx = __fadd_rn(pos[js * 3 + 0], -s_posi[0]);
            float dy = __fadd_rn(pos[js * 3 + 1], -s_posi[1]);
            float dz = __fadd_rn(pos[js * 3 + 2], -s_posi[2]);
            float d2v = __fadd_rn(__fadd_rn(__fmul_rn(dx, dx), __fmul_rn(dy, dy)),
                                  __fmul_rn(dz, dz));
            double d2d = (double)d2v;
            s_in2[t] = (d2d <= R2SQ) ? 1 : 0;
            s_in3[t] = (d2d <= R3SQ) ? 1 : 0;
            float dist = sqrtf(d2v);
            s_d[t] = dist;
            float inv = 1.0f / (dist + 1e-9f);
            float ux = dx * inv, uy = dy * inv, uz = dz * inv;
            float f0 = s_fri[0], f1 = s_fri[1], f2 = s_fri[2];
            float f3 = s_fri[3], f4 = s_fri[4], f5 = s_fri[5];
            float f6 = s_fri[6], f7 = s_fri[7], f8 = s_fri[8];
            s_feat[t][0] = f0 * ux + f1 * uy + f2 * uz;
            s_feat[t][1] = f3 * ux + f4 * uy + f5 * uz;
            s_feat[t][2] = f6 * ux + f7 * uy + f8 * uz;
            const float* op = ori + (size_t)js * 9;
            s_feat[t][3] = f0 * op[0] + f1 * op[1] + f2 * op[2];
            s_feat[t][4] = f3 * op[3] + f4 * op[4] + f5 * op[5];
            s_feat[t][5] = f6 * op[6] + f7 * op[7] + f8 * op[8];
            s_ds[t] = seq[js] - s_seqi;
        }
        __syncthreads();
        // --- Phase B1: edge weights per branch -> fp16 smem ---
        for (int task = t; task < ne * 16; task += 256) {   // branch 1
            int e = task >> 4, kk = task & 15;
            int dd = s_ds[e]; dd = max(-2, min(2, dd));
            int idx = dd + 2;
            const float* wr = s_W1 + idx * 112 + kk;
            float s = s_b1[idx * 16 + kk] + (s_d[e] / 2.7f) * wr[0];
#pragma unroll
            for (int cc = 0; cc < 6; cc++) s += s_feat[e][cc] * wr[(cc + 1) * 16];
            s = s > 0.0f ? s : 0.2f * s;
            s_wh[0][e][kk] = __float2half_rn(s);
        }
        for (int task = t; task < ne * 16; task += 256) {   // branch 2
            int e = task >> 4, kk = task & 15;
            float wv = 0.0f;
            if (s_in2[e]) {
                int dd = s_ds[e]; dd = max(-3, min(3, dd));
                int idx = dd + 3;
                const float* wr = s_W2 + idx * 112 + kk;
                float s = s_b2[idx * 16 + kk] + (s_d[e] / 1.8f) * wr[0];
#pragma unroll
                for (int cc = 0; cc < 6; cc++) s += s_feat[e][cc] * wr[(cc + 1) * 16];
                wv = s > 0.0f ? s : 0.2f * s;
            }
            s_wh[1][e][kk] = __float2half_rn(wv);
        }
        for (int task = t; task < ne * 16; task += 256) {   // branch 3
            int e = task >> 4, kk = task & 15;
            float wv = 0.0f;
            if (s_in3[e]) {
                int dd = s_ds[e]; dd = max(-5, min(5, dd));
                int idx = dd + 5;
                const float* wr = s_W3 + idx * 112 + kk;
                float s = s_b3[idx * 16 + kk] + (s_d[e] / 1.35f) * wr[0];
#pragma unroll
                for (int cc = 0; cc < 6; cc++) s += s_feat[e][cc] * wr[(cc + 1) * 16];
                wv = s > 0.0f ? s : 0.2f * s;
            }
            s_wh[2][e][kk] = __float2half_rn(wv);
        }
        // --- Phase B2: gather h0 rows, BN + lrelu, fp16 smem ---
        for (int task = t; task < ne * 16; task += 256) {
            int e = task >> 4, q = task & 15;
            int cc = q << 2;
            float4 v = *(const float4*)(h0 + (size_t)s_src[e] * 64 + cc);
            float u;
            u = v.x * s_sc[cc + 0] + s_bi[cc + 0]; v.x = u > 0.0f ? u : 0.1f * u;
            u = v.y * s_sc[cc + 1] + s_bi[cc + 1]; v.y = u > 0.0f ? u : 0.1f * u;
            u = v.z * s_sc[cc + 2] + s_bi[cc + 2]; v.z = u > 0.0f ? u : 0.1f * u;
            u = v.w * s_sc[cc + 3] + s_bi[cc + 3]; v.w = u > 0.0f ? u : 0.1f * u;
            union { __half2 h2[2]; uint2 uu; } cv;
            cv.h2[0] = __floats2half2_rn(v.x, v.y);
            cv.h2[1] = __floats2half2_rn(v.z, v.w);
            *(uint2*)&s_h[e][cc] = cv.uu;
        }
        // zero-fill padding edges (partial last tile)
        for (int task = t; task < (EB - ne) * 16; task += 256) {
            int e = ne + (task >> 4), q = task & 15;
            *(uint2*)&s_h[e][q << 2] = make_uint2(0u, 0u);
            s_wh[0][e][q] = __float2half_rn(0.0f);
            s_wh[1][e][q] = __float2half_rn(0.0f);
            s_wh[2][e][q] = __float2half_rn(0.0f);
        }
        __syncthreads();
        // --- Phase C: tensor-core accumulate (2 chunks of 16 edges) ---
#pragma unroll
        for (int ch = 0; ch < 2; ch++) {
            int ec = ch * 16;
            unsigned b0, b1;
            unsigned addrB = smem_u32(&s_h[ec + bero][w * 8]);
            asm volatile("ldmatrix.sync.aligned.m8n8.x2.trans.shared.b16 {%0,%1}, [%2];"
                         : "=r"(b0), "=r"(b1) : "r"(addrB));
            unsigned a0, a1, a2, a3;
            unsigned addrA = smem_u32(&s_wh[0][ec + aerow][amcol]);
            asm volatile("ldmatrix.sync.aligned.m8n8.x4.trans.shared.b16 {%0,%1,%2,%3}, [%4];"
                         : "=r"(a0), "=r"(a1), "=r"(a2), "=r"(a3) : "r"(addrA));
            asm volatile("mma.sync.aligned.m16n8k16.row.col.f32.f16.f16.f32 "
                         "{%0,%1,%2,%3}, {%4,%5,%6,%7}, {%8,%9}, {%0,%1,%2,%3};"
                         : "+f"(d1[0]), "+f"(d1[1]), "+f"(d1[2]), "+f"(d1[3])
                         : "r"(a0), "r"(a1), "r"(a2), "r"(a3), "r"(b0), "r"(b1));
            addrA = smem_u32(&s_wh[1][ec + aerow][amcol]);
            asm volatile("ldmatrix.sync.aligned.m8n8.x4.trans.shared.b16 {%0,%1,%2,%3}, [%4];"
                         : "=r"(a0), "=r"(a1), "=r"(a2), "=r"(a3) : "r"(addrA));
            asm volatile("mma.sync.aligned.m16n8k16.row.col.f32.f16.f16.f32 "
                         "{%0,%1,%2,%3}, {%4,%5,%6,%7}, {%8,%9}, {%0,%1,%2,%3};"
                         : "+f"(d2[0]), "+f"(d2[1]), "+f"(d2[2]), "+f"(d2[3])
                         : "r"(a0), "r"(a1), "r"(a2), "r"(a3), "r"(b0), "r"(b1));
            addrA = smem_u32(&s_wh[2][ec + aerow][amcol]);
            asm volatile("ldmatrix.sync.aligned.m8n8.x4.trans.shared.b16 {%0,%1,%2,%3}, [%4];"
                         : "=r"(a0), "=r"(a1), "=r"(a2), "=r"(a3) : "r"(addrA));
            asm volatile("mma.sync.aligned.m16n8k16.row.col.f32.f16.f16.f32 "
                         "{%0,%1,%2,%3}, {%4,%5,%6,%7}, {%8,%9}, {%0,%1,%2,%3};"
                         : "+f"(d3[0]), "+f"(d3[1]), "+f"(d3[2]), "+f"(d3[3])
                         : "r"(a0), "r"(a1), "r"(a2), "r"(a3), "r"(b0), "r"(b1));
        }
        __syncthreads();
    }
    // writeout: frag (rows g, g+8; cols w*8 + 2q, +1)
    int g = lane >> 2, q = lane & 3;
    size_t base = (size_t)i * AGGW;
    int c = w * 8 + q * 2;
    *(__half2*)(agg1 + base + (size_t)g * 64 + c)       = __floats2half2_rn(d1[0], d1[1]);
    *(__half2*)(agg1 + base + (size_t)(g + 8) * 64 + c) = __floats2half2_rn(d1[2], d1[3]);
    *(__half2*)(agg2 + base + (size_t)g * 64 + c)       = __floats2half2_rn(d2[0], d2[1]);
    *(__half2*)(agg2 + base + (size_t)(g + 8) * 64 + c) = __floats2half2_rn(d2[2], d2[3]);
    *(__half2*)(agg3 + base + (size_t)g * 64 + c)       = __floats2half2_rn(d3[0], d3[1]);
    *(__half2*)(agg3 + base + (size_t)(g + 8) * 64 + c) = __floats2half2_rn(d3[2], d3[3]);
}

// ---------------------------------------------------------------------------
// agg GEMMs, TENSOR CORE (HMMA m16n8k16), split-K (validated R11).
// ---------------------------------------------------------------------------
#define A_STRIDE 72
#define B_STRIDE 40
__global__ __launch_bounds__(128) void gemm_agg_k(
    const __half* __restrict__ agg1, const __half* __restrict__ agg2,
    const __half* __restrict__ agg3,
    const float* __restrict__ W1, const float* __restrict__ W2,
    const float* __restrict__ W3, float* __restrict__ part) {
    __shared__ __align__(16) __half As[64 * A_STRIDE];
    __shared__ __align__(16) __half Bsm[64 * B_STRIDE];
    int bx = blockIdx.x;
    int m0 = blockIdx.y * 64;
    int kz = blockIdx.z;
    const __half* A; const float* B; int ldb, coff, BN;
    if (bx == 0)      { A = agg1; B = W1; ldb = 32; coff = 0;  BN = 32; }
    else if (bx == 1) { A = agg2; B = W2; ldb = 16; coff = 32; BN = 16; }
    else              { A = agg3; B = W3; ldb = 16; coff = 48; BN = 16; }
    int t = threadIdx.x;
    int w = t >> 5, lane = t & 31;
    int nt_cnt = BN >> 3;
    float d[4][4];
#pragma unroll
    for (int i = 0; i < 4; i++)
#pragma unroll
        for (int j = 0; j < 4; j++) d[i][j] = 0.0f;
    int kbase = kz * (1024 / KSPLIT);

    int aseg = t & 7;
    int arow0 = t >> 3;
    int nf = ldb >> 2;
    int lrow = lane & 15;
    int lkoff = (lane >> 4) * 8;

    for (int ks = 0; ks < 1024 / KSPLIT; ks += 64) {
        int k0 = kbase + ks;
        __syncthreads();
#pragma unroll
        for (int j = 0; j < 4; j++) {
            int row = j * 16 + arow0;
            uint4 v = *(const uint4*)(A + (size_t)(m0 + row) * 1024 + k0 + aseg * 8);
            *(uint4*)&As[row * A_STRIDE + aseg * 8] = v;
        }
        for (int idx = t; idx < 64 * nf; idx += 128) {
            int row = idx / nf, cq = (idx % nf) << 2;
            float4 v = *(const float4*)(B + (size_t)(k0 + row) * ldb + cq);
            __half2 h01 = __floats2half2_rn(v.x, v.y);
            __half2 h23 = __floats2half2_rn(v.z, v.w);
            *(__half2*)&Bsm[row * B_STRIDE + cq] = h01;
            *(__half2*)&Bsm[row * B_STRIDE + cq + 2] = h23;
        }
        __syncthreads();
#pragma unroll
        for (int kk = 0; kk < 4; kk++) {
            unsigned a0, a1, a2, a3;
            unsigned addrA = smem_u32(&As[(w * 16 + lrow) * A_STRIDE + kk * 16 + lkoff]);
            asm volatile("ldmatrix.sync.aligned.m8n8.x4.shared.b16 {%0,%1,%2,%3}, [%4];"
                         : "=r"(a0), "=r"(a1), "=r"(a2), "=r"(a3) : "r"(addrA));
            for (int nt = 0; nt < nt_cnt; nt++) {
                unsigned b0, b1;
                unsigned addrB = smem_u32(&Bsm[(kk * 16 + lrow) * B_STRIDE + nt * 8]);
                asm volatile("ldmatrix.sync.aligned.m8n8.x2.trans.shared.b16 {%0,%1}, [%2];"
                             : "=r"(b0), "=r"(b1) : "r"(addrB));
                asm volatile("mma.sync.aligned.m16n8k16.row.col.f32.f16.f16.f32 "
                             "{%0,%1,%2,%3}, {%4,%5,%6,%7}, {%8,%9}, {%0,%1,%2,%3};"
                             : "+f"(d[nt][0]), "+f"(d[nt][1]), "+f"(d[nt][2]), "+f"(d[nt][3])
                             : "r"(a0), "r"(a1), "r"(a2), "r"(a3), "r"(b0), "r"(b1));
            }
        }
    }
    float* P = part + (size_t)kz * (N_NODES * 64);
    int g = lane >> 2, q = lane & 3;
    size_t r0 = (size_t)(m0 + w * 16 + g);
    for (int nt = 0; nt < nt_cnt; nt++) {
        int c = coff + nt * 8 + q * 2;
        *(float2*)&P[r0 * 64 + c] = make_float2(d[nt][0], d[nt][1]);
        *(float2*)&P[(r0 + 8) * 64 + c] = make_float2(d[nt][2], d[nt][3]);
    }
}

// ---------------------------------------------------------------------------
// reduce_k: cat = sum of KSPLIT split-K partials; emit per-block cat stats.
// ---------------------------------------------------------------------------
__global__ __launch_bounds__(256) void reduce_k(
    const float* __restrict__ part, float* __restrict__ cat,
    float* __restrict__ stats_c) {
    __shared__ float cs[64], cq[64];
    int by = blockIdx.x;
    int t = threadIdx.x;
    if (t < 64) { cs[t] = 0.0f; cq[t] = 0.0f; }
    __syncthreads();
    int r0 = (t >> 4) * 4;
    int c = (t & 15) * 4;
    float s[4] = {0, 0, 0, 0}, q[4] = {0, 0, 0, 0};
#pragma unroll
    for (int j = 0; j < 4; j++) {
        size_t off = ((size_t)(by * 64 + r0 + j)) * 64 + c;
        float4 v = make_float4(0.f, 0.f, 0.f, 0.f);
#pragma unroll
        for (int p = 0; p < KSPLIT; p++) {
            float4 u = *(const float4*)(part + (size_t)p * (N_NODES * 64) + off);
            v.x += u.x; v.y += u.y; v.z += u.z; v.w += u.w;
        }
        *(float4*)(cat + off) = v;
        s[0] += v.x; q[0] += v.x * v.x;
        s[1] += v.y; q[1] += v.y * v.y;
        s[2] += v.z; q[2] += v.z * v.z;
        s[3] += v.w; q[3] += v.w * v.w;
    }
#pragma unroll
    for (int j = 0; j < 4; j++) {
        atomicAdd(&cs[c + j], s[j]);
        atomicAdd(&cq[c + j], q[j]);
    }
    __syncthreads();
    if (t < 64) {
        stats_c[by * 128 + t] = cs[t];
        stats_c[by * 128 + 64 + t] = cq[t];
    }
}

// ---------------------------------------------------------------------------
// Output GEMM: out += lrelu(bn_out(cat)) @ out_W   [4096,64]x[64,256]
// ---------------------------------------------------------------------------
__global__ __launch_bounds__(256) void gemm_out_k(
    const float* __restrict__ cat, const float* __restrict__ stats_c,
    const float* __restrict__ out_g, const float* __restrict__ out_b,
    const float* __restrict__ outW, float* __restrict__ out) {
    __shared__ float s_sc[64], s_bi[64];
    __shared__ __align__(16) float As[16][65];
    __shared__ __align__(16) float Bs[16][64];
    int t = threadIdx.x;
    bn_fold(stats_c, 64, 64, out_g, out_b, s_sc, s_bi, t, 256);
    int n0 = blockIdx.x * 64;
    int m0 = blockIdx.y * 64;
    int tx = t & 15, ty = t >> 4;
    int lam = t >> 2, lak = (t & 3) << 2;
    int lbk = t >> 4, lbn = (t & 15) << 2;
    float acc[4][4];
#pragma unroll
    for (int r = 0; r < 4; r++)
#pragma unroll
        for (int cc = 0; cc < 4; cc++) acc[r][cc] = 0.0f;
    __syncthreads();

    for (int k0 = 0; k0 < 64; k0 += 16) {
        float4 av = *(const float4*)(cat + (size_t)(m0 + lam) * 64 + k0 + lak);
        float v;
        v = av.x * s_sc[k0 + lak + 0] + s_bi[k0 + lak + 0]; av.x = v > 0.0f ? v : 0.1f * v;
        v = av.y * s_sc[k0 + lak + 1] + s_bi[k0 + lak + 1]; av.y = v > 0.0f ? v : 0.1f * v;
        v = av.z * s_sc[k0 + lak + 2] + s_bi[k0 + lak + 2]; av.z = v > 0.0f ? v : 0.1f * v;
        v = av.w * s_sc[k0 + lak + 3] + s_bi[k0 + lak + 3]; av.w = v > 0.0f ? v : 0.1f * v;
        As[lak + 0][lam] = av.x;
        As[lak + 1][lam] = av.y;
        As[lak + 2][lam] = av.z;
        As[lak + 3][lam] = av.w;
        float4 bv = *(const float4*)(outW + (size_t)(k0 + lbk) * 256 + n0 + lbn);
        *(float4*)&Bs[lbk][lbn] = bv;
        __syncthreads();
#pragma unroll
        for (int kk = 0; kk < 16; kk++) {
            float a0 = As[kk][ty * 4 + 0];
            float a1 = As[kk][ty * 4 + 1];
            float a2 = As[kk][ty * 4 + 2];
            float a3 = As[kk][ty * 4 + 3];
            float4 b = *(const float4*)&Bs[kk][tx * 4];
            acc[0][0] += a0 * b.x; acc[0][1] += a0 * b.y; acc[0][2] += a0 * b.z; acc[0][3] += a0 * b.w;
            acc[1][0] += a1 * b.x; acc[1][1] += a1 * b.y; acc[1][2] += a1 * b.z; acc[1][3] += a1 * b.w;
            acc[2][0] += a2 * b.x; acc[2][1] += a2 * b.y; acc[2][2] += a2 * b.z; acc[2][3] += a2 * b.w;
            acc[3][0] += a3 * b.x; acc[3][1] += a3 * b.y; acc[3][2] += a3 * b.z; acc[3][3] += a3 * b.w;
        }
        __syncthreads();
    }
#pragma unroll
    for (int r = 0; r < 4; r++) {
        size_t m = m0 + ty * 4 + r;
#pragma unroll
        for (int cc = 0; cc < 4; cc++) {
            float* p = out + m * 256 + n0 + tx * 4 + cc;
            *p += acc[r][cc];
        }
    }
}

// ---------------------------------------------------------------------------
// Launch
// ---------------------------------------------------------------------------
extern "C" void kernel_launch(void* const* d_in, const int* in_sizes, int n_in,
                              void* d_out, int out_size) {
    const float* x    = (const float*)d_in[0];
    const float* pos  = (const float*)d_in[1];
    const float* ori  = (const float*)d_in[2];
    const int*   seq  = (const int*)d_in[3];
    // d_in[4] = batch (implied by graph)
    const int* src1 = (const int*)d_in[5];
    const int* dst1 = (const int*)d_in[6];
    // src2/dst2, src3/dst3 unused: nested-radius property recovers them
    const float* id_g = (const float*)d_in[11];
    const float* id_b = (const float*)d_in[12];
    const float* id_W = (const float*)d_in[13];
    const float* in_g = (const float*)d_in[14];
    const float* in_b = (const float*)d_in[15];
    const float* in_W = (const float*)d_in[16];
    const float* mid_g = (const float*)d_in[17];
    const float* mid_b = (const float*)d_in[18];
    const float* Ws1 = (const float*)d_in[19];
    const float* bs1 = (const float*)d_in[20];
    const float* W1  = (const float*)d_in[21];
    const float* Ws2 = (const float*)d_in[22];
    const float* bs2 = (const float*)d_in[23];
    const float* W2  = (const float*)d_in[24];
    const float* Ws3 = (const float*)d_in[25];
    const float* bs3 = (const float*)d_in[26];
    const float* W3  = (const float*)d_in[27];
    const float* out_g = (const float*)d_in[28];
    const float* out_b = (const float*)d_in[29];
    const float* out_W = (const float*)d_in[30];
    float* out = (float*)d_out;

    int E1 = in_sizes[5];

    float *h0, *cat, *part, *stats, *sb;
    __half *agg1, *agg2, *agg3;
    int* ro;
    cudaGetSymbolAddress((void**)&h0, g_h0);
    cudaGetSymbolAddress((void**)&agg1, g_agg1);
    cudaGetSymbolAddress((void**)&agg2, g_agg2);
    cudaGetSymbolAddress((void**)&agg3, g_agg3);
    cudaGetSymbolAddress((void**)&cat, g_cat);
    cudaGetSymbolAddress((void**)&part, g_part);
    cudaGetSymbolAddress((void**)&stats, g_stats);
    cudaGetSymbolAddress((void**)&sb, g_sb);
    cudaGetSymbolAddress((void**)&ro, g_ro);
    float* stats_x = stats;              // 16 slots * 256
    float* stats_h = stats + 4096;       // 64 slots * 128
    float* stats_c = stats + 12288;      // 64 slots * 128

    // 1. x column stats + branch-1 CSR
    prep_k<<<33, 256>>>(x, dst1, E1, stats_x, ro);
    // 2. identity GEMM -> out, input GEMM -> h0 (+ h0 stats)
    gemm_x_k<<<dim3(5, 64), 256>>>(x, stats_x, id_g, id_b, id_W,
                                   in_g, in_b, in_W, out, h0, stats_h);
    // 3. fold mid-BN once
    fold_bn_k<<<1, 64>>>(stats_h, mid_g, mid_b, sb);
    // 4. fused 3-branch edge aggregation, tensor-core Phase C
    edge_all_k<<<N_NODES, 256>>>(h0, pos, ori, seq, src1, ro,
                                 Ws1, bs1, Ws2, bs2, Ws3, bs3,
                                 sb, agg1, agg2, agg3);
    // 5. agg GEMMs, tensor-core HMMA, split-K (768 blocks)
    gemm_agg_k<<<dim3(3, 64, KSPLIT), 128>>>(agg1, agg2, agg3, W1, W2, W3, part);
    // 6. reduce partials -> cat (+ cat stats)
    reduce_k<<<64, 256>>>(part, cat, stats_c);
    // 7. output GEMM, accumulate onto identity
    gemm_out_k<<<dim3(4, 64), 256>>>(cat, stats_c, out_g, out_b, out_W, out);
}

// round 14
// speedup vs baseline: 1.2875x; 1.0535x over previous
#include <cuda_runtime.h>
#include <cuda_fp16.h>

// ---------------------------------------------------------------------------
// Problem constants
// ---------------------------------------------------------------------------
#define N_NODES 4096
#define AGGW    1024     // K(16) * WIDTH(64)
#define KSPLIT  4

__device__ __forceinline__ unsigned smem_u32(const void* p) {
    return (unsigned)__cvta_generic_to_shared(p);
}

// ---------------------------------------------------------------------------
// Scratch (device globals -- no allocation allowed). 16B-aligned for float4.
// ---------------------------------------------------------------------------
__device__ __align__(16) float g_h0[N_NODES * 64];
__device__ __align__(16) __half g_agg1[N_NODES * AGGW];
__device__ __align__(16) __half g_agg2[N_NODES * AGGW];
__device__ __align__(16) __half g_agg3[N_NODES * AGGW];
__device__ __align__(16) float g_cat[N_NODES * 64];
__device__ __align__(16) float g_part[KSPLIT * N_NODES * 64];   // split-K partials
// partial column stats: x: 16 slots * 256 = 4096
//                       h0: 64 slots * 128 = 8192 at offset 4096
//                       cat: 64 slots * 128 = 8192 at offset 12288
__device__ float g_stats[20480];
__device__ float g_sb[128];          // mid-BN folded scale[0:64) / bias[64:128)
__device__ int   g_ro[N_NODES + 1];

// ---------------------------------------------------------------------------
// BN fold: reduce nslots partial (sum, sq) -> per-channel scale/bias in smem
// ---------------------------------------------------------------------------
__device__ __forceinline__ void bn_fold(const float* __restrict__ stats, int C,
                                        int nslots,
                                        const float* __restrict__ g,
                                        const float* __restrict__ b,
                                        float* s_sc, float* s_bi,
                                        int t, int nthreads) {
    for (int c = t; c < C; c += nthreads) {
        float s = 0.0f, q = 0.0f;
        for (int bk = 0; bk < nslots; bk++) {
            s += stats[bk * 2 * C + c];
            q += stats[bk * 2 * C + C + c];
        }
        float m = s * (1.0f / N_NODES);
        float v = q * (1.0f / N_NODES) - m * m;
        float rs = rsqrtf(v + 1e-5f);
        float sc = rs * g[c];
        s_sc[c] = sc;
        s_bi[c] = b[c] - m * sc;
    }
}

// ---------------------------------------------------------------------------
// fold_bn_k: one block, folds the 64-slot h0 stats into g_sb once
// ---------------------------------------------------------------------------
__global__ void fold_bn_k(const float* __restrict__ stats,
                          const float* __restrict__ g,
                          const float* __restrict__ b,
                          float* __restrict__ sb) {
    int c = threadIdx.x;   // 64 threads
    float s = 0.0f, q = 0.0f;
    for (int bk = 0; bk < 64; bk++) {
        s += stats[bk * 128 + c];
        q += stats[bk * 128 + 64 + c];
    }
    float m = s * (1.0f / N_NODES);
    float v = q * (1.0f / N_NODES) - m * m;
    float rs = rsqrtf(v + 1e-5f);
    float sc = rs * g[c];
    sb[c] = sc;
    sb[64 + c] = b[c] - m * sc;
}

// ---------------------------------------------------------------------------
// prep: blocks 0..15 -> partial column stats of x (C=128)
//       blocks 16..32 -> CSR row offsets for branch-1 dst (binary search)
// ---------------------------------------------------------------------------
__global__ void prep_k(const float* __restrict__ x, const int* __restrict__ dst,
                       int E, float* __restrict__ stats_x, int* __restrict__ ro) {
    int bx = blockIdx.x;
    if (bx < 16) {
        int c = threadIdx.x;
        if (c < 128) {
            int r0 = bx * 256;
            float s = 0.0f, s2 = 0.0f;
            for (int r = r0; r < r0 + 256; r++) {
                float v = x[(size_t)r * 128 + c];
                s += v;
                s2 += v * v;
            }
            stats_x[bx * 256 + c] = s;
            stats_x[bx * 256 + 128 + c] = s2;
        }
    } else {
        int t = (bx - 16) * 256 + threadIdx.x;
        if (t > N_NODES) return;
        if (t == N_NODES) { ro[t] = E; return; }
        int lo = 0, hi = E;
        while (lo < hi) {
            int mid = (lo + hi) >> 1;
            if (dst[mid] < t) lo = mid + 1; else hi = mid;
        }
        ro[t] = lo;
    }
}

// ---------------------------------------------------------------------------
// gemm_x: merged identity + input GEMMs on A = x [4096,128].
// ---------------------------------------------------------------------------
__global__ __launch_bounds__(256) void gemm_x_k(
    const float* __restrict__ x, const float* __restrict__ stats_x,
    const float* __restrict__ id_g, const float* __restrict__ id_b,
    const float* __restrict__ idW,
    const float* __restrict__ in_g, const float* __restrict__ in_b,
    const float* __restrict__ inW,
    float* __restrict__ out, float* __restrict__ h0,
    float* __restrict__ stats_h) {
    __shared__ float s_sc[128], s_bi[128];
    __shared__ __align__(16) float As[16][65];
    __shared__ __align__(16) float Bs[16][64];
    __shared__ float hs[64], hq[64];
    int t = threadIdx.x;
    int bx = blockIdx.x;
    bool idp = bx < 4;
    bn_fold(stats_x, 128, 16, idp ? id_g : in_g, idp ? id_b : in_b, s_sc, s_bi, t, 256);

    const float* B = idp ? idW : inW;
    int Nd = idp ? 256 : 64;
    int n0 = idp ? bx * 64 : 0;
    float* C = idp ? out : h0;
    int m0 = blockIdx.y * 64;
    int tx = t & 15, ty = t >> 4;
    int lam = t >> 2, lak = (t & 3) << 2;
    int lbk = t >> 4, lbn = (t & 15) << 2;
    float acc[4][4];
#pragma unroll
    for (int r = 0; r < 4; r++)
#pragma unroll
        for (int cc = 0; cc < 4; cc++) acc[r][cc] = 0.0f;
    if (t < 64) { hs[t] = 0.0f; hq[t] = 0.0f; }
    __syncthreads();

    for (int k0 = 0; k0 < 128; k0 += 16) {
        float4 av = *(const float4*)(x + (size_t)(m0 + lam) * 128 + k0 + lak);
        float v;
        v = av.x * s_sc[k0 + lak + 0] + s_bi[k0 + lak + 0]; av.x = v > 0.0f ? v : 0.1f * v;
        v = av.y * s_sc[k0 + lak + 1] + s_bi[k0 + lak + 1]; av.y = v > 0.0f ? v : 0.1f * v;
        v = av.z * s_sc[k0 + lak + 2] + s_bi[k0 + lak + 2]; av.z = v > 0.0f ? v : 0.1f * v;
        v = av.w * s_sc[k0 + lak + 3] + s_bi[k0 + lak + 3]; av.w = v > 0.0f ? v : 0.1f * v;
        As[lak + 0][lam] = av.x;
        As[lak + 1][lam] = av.y;
        As[lak + 2][lam] = av.z;
        As[lak + 3][lam] = av.w;
        float4 bv = *(const float4*)(B + (size_t)(k0 + lbk) * Nd + n0 + lbn);
        *(float4*)&Bs[lbk][lbn] = bv;
        __syncthreads();
#pragma unroll
        for (int kk = 0; kk < 16; kk++) {
            float a0 = As[kk][ty * 4 + 0];
            float a1 = As[kk][ty * 4 + 1];
            float a2 = As[kk][ty * 4 + 2];
            float a3 = As[kk][ty * 4 + 3];
            float4 b = *(const float4*)&Bs[kk][tx * 4];
            acc[0][0] += a0 * b.x; acc[0][1] += a0 * b.y; acc[0][2] += a0 * b.z; acc[0][3] += a0 * b.w;
            acc[1][0] += a1 * b.x; acc[1][1] += a1 * b.y; acc[1][2] += a1 * b.z; acc[1][3] += a1 * b.w;
            acc[2][0] += a2 * b.x; acc[2][1] += a2 * b.y; acc[2][2] += a2 * b.z; acc[2][3] += a2 * b.w;
            acc[3][0] += a3 * b.x; acc[3][1] += a3 * b.y; acc[3][2] += a3 * b.z; acc[3][3] += a3 * b.w;
        }
        __syncthreads();
    }
#pragma unroll
    for (int r = 0; r < 4; r++) {
        int m = m0 + ty * 4 + r;
#pragma unroll
        for (int cc = 0; cc < 4; cc++)
            C[(size_t)m * Nd + n0 + tx * 4 + cc] = acc[r][cc];
    }
    if (!idp) {
#pragma unroll
        for (int cc = 0; cc < 4; cc++) {
            float s = acc[0][cc] + acc[1][cc] + acc[2][cc] + acc[3][cc];
            float q = acc[0][cc] * acc[0][cc] + acc[1][cc] * acc[1][cc] +
                      acc[2][cc] * acc[2][cc] + acc[3][cc] * acc[3][cc];
            atomicAdd(&hs[tx * 4 + cc], s);
            atomicAdd(&hq[tx * 4 + cc], q);
        }
        __syncthreads();
        if (t < 64) {
            stats_h[blockIdx.y * 128 + t] = hs[t];
            stats_h[blockIdx.y * 128 + 64 + t] = hq[t];
        }
    }
}

// ---------------------------------------------------------------------------
// Fused edge aggregation, TENSOR-CORE Phase C, EB=64, vectorized Phase B1:
//   B1 tasks compute k-PAIRS with float2 weight loads (Ws k-contiguous).
// ---------------------------------------------------------------------------
#define EB 64
#define WST 24    // s_wh row stride in halves
#define HST 72    // s_h row stride in halves
__global__ __launch_bounds__(256) void edge_all_k(
    const float* __restrict__ h0, const float* __restrict__ pos,
    const float* __restrict__ ori, const int* __restrict__ seq,
    const int* __restrict__ src, const int* __restrict__ ro,
    const float* __restrict__ Ws1, const float* __restrict__ bs1,
    const float* __restrict__ Ws2, const float* __restrict__ bs2,
    const float* __restrict__ Ws3, const float* __restrict__ bs3,
    const float* __restrict__ sb,
    __half* __restrict__ agg1, __half* __restrict__ agg2,
    __half* __restrict__ agg3) {
    const double R2SQ = 1.8 * 1.8;
    const double R3T  = 0.75 * 1.8;
    const double R3SQ = R3T * R3T;
    __shared__ float s_sc[64], s_bi[64];
    __shared__ __align__(16) float s_W1[5 * 112];
    __shared__ __align__(16) float s_b1[5 * 16];
    __shared__ __align__(16) float s_W2[7 * 112];
    __shared__ __align__(16) float s_b2[7 * 16];
    __shared__ __align__(16) float s_W3[11 * 112];
    __shared__ __align__(16) float s_b3[11 * 16];
    __shared__ float s_fri[9];
    __shared__ float s_posi[3];
    __shared__ int   s_seqi;
    __shared__ float s_d[EB];
    __shared__ int   s_in2[EB], s_in3[EB];
    __shared__ float s_feat[EB][6];
    __shared__ int   s_ds[EB], s_src[EB];
    __shared__ __align__(16) __half s_wh[3][EB][WST];   // w per branch, [edge][k]
    __shared__ __align__(16) __half s_h[EB][HST];       // h fp16 [edge][c]

    int i = blockIdx.x;
    int t = threadIdx.x;
    if (t < 128) { if (t < 64) s_sc[t] = sb[t]; else s_bi[t - 64] = sb[t]; }
    for (int j = t; j < 5 * 112; j += 256)  s_W1[j] = Ws1[j];
    for (int j = t; j < 5 * 16; j += 256)   s_b1[j] = bs1[j];
    for (int j = t; j < 7 * 112; j += 256)  s_W2[j] = Ws2[j];
    for (int j = t; j < 7 * 16; j += 256)   s_b2[j] = bs2[j];
    for (int j = t; j < 11 * 112; j += 256) s_W3[j] = Ws3[j];
    for (int j = t; j < 11 * 16; j += 256)  s_b3[j] = bs3[j];
    if (t < 9)  s_fri[t] = ori[i * 9 + t];
    if (t >= 9 && t < 12) s_posi[t - 9] = pos[i * 3 + (t - 9)];
    if (t == 12) s_seqi = seq[i];

    int start = ro[i], end = ro[i + 1];
    int w = t >> 5, lane = t & 31;
    int aerow = ((lane >> 4) & 1) * 8 + (lane & 7);   // A (.x4.trans): edge row
    int amcol = ((lane >> 3) & 1) * 8;                // A: m col-group (halves)
    int bero = lane & 15;                             // B (.x2.trans): edge row
    float d1[4], d2[4], d3[4];
#pragma unroll
    for (int j = 0; j < 4; j++) { d1[j] = 0.0f; d2[j] = 0.0f; d3[j] = 0.0f; }
    __syncthreads();

    for (int e0 = start; e0 < end; e0 += EB) {
        int ne = min(EB, end - e0);
        // --- Phase A: per-edge geometry (1 thread per edge) ---
        if (t < ne) {
            int js = src[e0 + t];
            s_src[t] = js;
            float dx = __fadd_rn(pos[js * 3 + 0], -s_posi[0]);
            float dy = __fadd_rn(pos[js * 3 + 1], -s_posi[1]);
            float dz = __fadd_rn(pos[js * 3 + 2], -s_posi[2]);
            float d2v = __fadd_rn(__fadd_rn(__fmul_rn(dx, dx), __fmul_rn(dy, dy)),
                                  __fmul_rn(dz, dz));
            double d2d = (double)d2v;
            s_in2[t] = (d2d <= R2SQ) ? 1 : 0;
            s_in3[t] = (d2d <= R3SQ) ? 1 : 0;
            float dist = sqrtf(d2v);
            s_d[t] = dist;
            float inv = 1.0f / (dist + 1e-9f);
            float ux = dx * inv, uy = dy * inv, uz = dz * inv;
            float f0 = s_fri[0], f1 = s_fri[1], f2 = s_fri[2];
            float f3 = s_fri[3], f4 = s_fri[4], f5 = s_fri[5];
            float f6 = s_fri[6], f7 = s_fri[7], f8 = s_fri[8];
            s_feat[t][0] = f0 * ux + f1 * uy + f2 * uz;
            s_feat[t][1] = f3 * ux + f4 * uy + f5 * uz;
            s_feat[t][2] = f6 * ux + f7 * uy + f8 * uz;
            const float* op = ori + (size_t)js * 9;
            s_feat[t][3] = f0 * op[0] + f1 * op[1] + f2 * op[2];
            s_feat[t][4] = f3 * op[3] + f4 * op[4] + f5 * op[5];
            s_feat[t][5] = f6 * op[6] + f7 * op[7] + f8 * op[8];
            s_ds[t] = seq[js] - s_seqi;
        }
        __syncthreads();
        // --- Phase B1 (vectorized): k-pairs with float2 weight loads ---
        for (int task = t; task < ne * 8; task += 256) {    // branch 1
            int e = task >> 3, kq = (task & 7) << 1;        // k pair base
            int dd = s_ds[e]; dd = max(-2, min(2, dd));
            const float* wr = s_W1 + (dd + 2) * 112 + kq;
            float2 sv = *(const float2*)(s_b1 + (dd + 2) * 16 + kq);
            float dscale = s_d[e] / 2.7f;
            float2 wv = *(const float2*)(wr);
            sv.x += dscale * wv.x; sv.y += dscale * wv.y;
#pragma unroll
            for (int cc = 0; cc < 6; cc++) {
                float f = s_feat[e][cc];
                wv = *(const float2*)(wr + (cc + 1) * 16);
                sv.x += f * wv.x; sv.y += f * wv.y;
            }
            sv.x = sv.x > 0.0f ? sv.x : 0.2f * sv.x;
            sv.y = sv.y > 0.0f ? sv.y : 0.2f * sv.y;
            *(__half2*)&s_wh[0][e][kq] = __floats2half2_rn(sv.x, sv.y);
        }
        for (int task = t; task < ne * 8; task += 256) {    // branch 2
            int e = task >> 3, kq = (task & 7) << 1;
            float2 sv = make_float2(0.0f, 0.0f);
            if (s_in2[e]) {
                int dd = s_ds[e]; dd = max(-3, min(3, dd));
                const float* wr = s_W2 + (dd + 3) * 112 + kq;
                sv = *(const float2*)(s_b2 + (dd + 3) * 16 + kq);
                float dscale = s_d[e] / 1.8f;
                float2 wv = *(const float2*)(wr);
                sv.x += dscale * wv.x; sv.y += dscale * wv.y;
#pragma unroll
                for (int cc = 0; cc < 6; cc++) {
                    float f = s_feat[e][cc];
                    wv = *(const float2*)(wr + (cc + 1) * 16);
                    sv.x += f * wv.x; sv.y += f * wv.y;
                }
                sv.x = sv.x > 0.0f ? sv.x : 0.2f * sv.x;
                sv.y = sv.y > 0.0f ? sv.y : 0.2f * sv.y;
            }
            *(__half2*)&s_wh[1][e][kq] = __floats2half2_rn(sv.x, sv.y);
        }
        for (int task = t; task < ne * 8; task += 256) {    // branch 3
            int e = task >> 3, kq = (task & 7) << 1;
            float2 sv = make_float2(0.0f, 0.0f);
            if (s_in3[e]) {
                int dd = s_ds[e]; dd = max(-5, min(5, dd));
                const float* wr = s_W3 + (dd + 5) * 112 + kq;
                sv = *(const float2*)(s_b3 + (dd + 5) * 16 + kq);
                float dscale = s_d[e] / 1.35f;
                float2 wv = *(const float2*)(wr);
                sv.x += dscale * wv.x; sv.y += dscale * wv.y;
#pragma unroll
                for (int cc = 0; cc < 6; cc++) {
                    float f = s_feat[e][cc];
                    wv = *(const float2*)(wr + (cc + 1) * 16);
                    sv.x += f * wv.x; sv.y += f * wv.y;
                }
                sv.x = sv.x > 0.0f ? sv.x : 0.2f * sv.x;
                sv.y = sv.y > 0.0f ? sv.y : 0.2f * sv.y;
            }
            *(__half2*)&s_wh[2][e][kq] = __floats2half2_rn(sv.x, sv.y);
        }
        // --- Phase B2: gather h0 rows, BN + lrelu, fp16 smem ---
        for (int task = t; task < ne * 16; task += 256) {
            int e = task >> 4, q = task & 15;
            int cc = q << 2;
            float4 v = *(const float4*)(h0 + (size_t)s_src[e] * 64 + cc);
            float u;
            u = v.x * s_sc[cc + 0] + s_bi[cc + 0]; v.x = u > 0.0f ? u : 0.1f * u;
            u = v.y * s_sc[cc + 1] + s_bi[cc + 1]; v.y = u > 0.0f ? u : 0.1f * u;
            u = v.z * s_sc[cc + 2] + s_bi[cc + 2]; v.z = u > 0.0f ? u : 0.1f * u;
            u = v.w * s_sc[cc + 3] + s_bi[cc + 3]; v.w = u > 0.0f ? u : 0.1f * u;
            union { __half2 h2[2]; uint2 uu; } cv;
            cv.h2[0] = __floats2half2_rn(v.x, v.y);
            cv.h2[1] = __floats2half2_rn(v.z, v.w);
            *(uint2*)&s_h[e][cc] = cv.uu;
        }
        // zero-fill padding edges (partial last tile)
        for (int task = t; task < (EB - ne) * 16; task += 256) {
            int e = ne + (task >> 4), q = task & 15;
            *(uint2*)&s_h[e][q << 2] = make_uint2(0u, 0u);
            s_wh[0][e][q] = __float2half_rn(0.0f);
            s_wh[1][e][q] = __float2half_rn(0.0f);
            s_wh[2][e][q] = __float2half_rn(0.0f);
        }
        __syncthreads();
        // --- Phase C: tensor-core accumulate (4 chunks of 16 edges) ---
#pragma unroll
        for (int ch = 0; ch < 4; ch++) {
            int ec = ch * 16;
            unsigned b0, b1;
            unsigned addrB = smem_u32(&s_h[ec + bero][w * 8]);
            asm volatile("ldmatrix.sync.aligned.m8n8.x2.trans.shared.b16 {%0,%1}, [%2];"
                         : "=r"(b0), "=r"(b1) : "r"(addrB));
            unsigned a0, a1, a2, a3;
            unsigned addrA = smem_u32(&s_wh[0][ec + aerow][amcol]);
            asm volatile("ldmatrix.sync.aligned.m8n8.x4.trans.shared.b16 {%0,%1,%2,%3}, [%4];"
                         : "=r"(a0), "=r"(a1), "=r"(a2), "=r"(a3) : "r"(addrA));
            asm volatile("mma.sync.aligned.m16n8k16.row.col.f32.f16.f16.f32 "
                         "{%0,%1,%2,%3}, {%4,%5,%6,%7}, {%8,%9}, {%0,%1,%2,%3};"
                         : "+f"(d1[0]), "+f"(d1[1]), "+f"(d1[2]), "+f"(d1[3])
                         : "r"(a0), "r"(a1), "r"(a2), "r"(a3), "r"(b0), "r"(b1));
            addrA = smem_u32(&s_wh[1][ec + aerow][amcol]);
            asm volatile("ldmatrix.sync.aligned.m8n8.x4.trans.shared.b16 {%0,%1,%2,%3}, [%4];"
                         : "=r"(a0), "=r"(a1), "=r"(a2), "=r"(a3) : "r"(addrA));
            asm volatile("mma.sync.aligned.m16n8k16.row.col.f32.f16.f16.f32 "
                         "{%0,%1,%2,%3}, {%4,%5,%6,%7}, {%8,%9}, {%0,%1,%2,%3};"
                         : "+f"(d2[0]), "+f"(d2[1]), "+f"(d2[2]), "+f"(d2[3])
                         : "r"(a0), "r"(a1), "r"(a2), "r"(a3), "r"(b0), "r"(b1));
            addrA = smem_u32(&s_wh[2][ec + aerow][amcol]);
            asm volatile("ldmatrix.sync.aligned.m8n8.x4.trans.shared.b16 {%0,%1,%2,%3}, [%4];"
                         : "=r"(a0), "=r"(a1), "=r"(a2), "=r"(a3) : "r"(addrA));
            asm volatile("mma.sync.aligned.m16n8k16.row.col.f32.f16.f16.f32 "
                         "{%0,%1,%2,%3}, {%4,%5,%6,%7}, {%8,%9}, {%0,%1,%2,%3};"
                         : "+f"(d3[0]), "+f"(d3[1]), "+f"(d3[2]), "+f"(d3[3])
                         : "r"(a0), "r"(a1), "r"(a2), "r"(a3), "r"(b0), "r"(b1));
        }
        __syncthreads();
    }
    // writeout: frag (rows g, g+8; cols w*8 + 2q, +1)
    int g = lane >> 2, q = lane & 3;
    size_t base = (size_t)i * AGGW;
    int c = w * 8 + q * 2;
    *(__half2*)(agg1 + base + (size_t)g * 64 + c)       = __floats2half2_rn(d1[0], d1[1]);
    *(__half2*)(agg1 + base + (size_t)(g + 8) * 64 + c) = __floats2half2_rn(d1[2], d1[3]);
    *(__half2*)(agg2 + base + (size_t)g * 64 + c)       = __floats2half2_rn(d2[0], d2[1]);
    *(__half2*)(agg2 + base + (size_t)(g + 8) * 64 + c) = __floats2half2_rn(d2[2], d2[3]);
    *(__half2*)(agg3 + base + (size_t)g * 64 + c)       = __floats2half2_rn(d3[0], d3[1]);
    *(__half2*)(agg3 + base + (size_t)(g + 8) * 64 + c) = __floats2half2_rn(d3[2], d3[3]);
}

// ---------------------------------------------------------------------------
// agg GEMMs, TENSOR CORE (HMMA m16n8k16), split-K (validated R11).
// ---------------------------------------------------------------------------
#define A_STRIDE 72
#define B_STRIDE 40
__global__ __launch_bounds__(128) void gemm_agg_k(
    const __half* __restrict__ agg1, const __half* __restrict__ agg2,
    const __half* __restrict__ agg3,
    const float* __restrict__ W1, const float* __restrict__ W2,
    const float* __restrict__ W3, float* __restrict__ part) {
    __shared__ __align__(16) __half As[64 * A_STRIDE];
    __shared__ __align__(16) __half Bsm[64 * B_STRIDE];
    int bx = blockIdx.x;
    int m0 = blockIdx.y * 64;
    int kz = blockIdx.z;
    const __half* A; const float* B; int ldb, coff, BN;
    if (bx == 0)      { A = agg1; B = W1; ldb = 32; coff = 0;  BN = 32; }
    else if (bx == 1) { A = agg2; B = W2; ldb = 16; coff = 32; BN = 16; }
    else              { A = agg3; B = W3; ldb = 16; coff = 48; BN = 16; }
    int t = threadIdx.x;
    int w = t >> 5, lane = t & 31;
    int nt_cnt = BN >> 3;
    float d[4][4];
#pragma unroll
    for (int i = 0; i < 4; i++)
#pragma unroll
        for (int j = 0; j < 4; j++) d[i][j] = 0.0f;
    int kbase = kz * (1024 / KSPLIT);

    int aseg = t & 7;
    int arow0 = t >> 3;
    int nf = ldb >> 2;
    int lrow = lane & 15;
    int lkoff = (lane >> 4) * 8;

    for (int ks = 0; ks < 1024 / KSPLIT; ks += 64) {
        int k0 = kbase + ks;
        __syncthreads();
#pragma unroll
        for (int j = 0; j < 4; j++) {
            int row = j * 16 + arow0;
            uint4 v = *(const uint4*)(A + (size_t)(m0 + row) * 1024 + k0 + aseg * 8);
            *(uint4*)&As[row * A_STRIDE + aseg * 8] = v;
        }
        for (int idx = t; idx < 64 * nf; idx += 128) {
            int row = idx / nf, cq = (idx % nf) << 2;
            float4 v = *(const float4*)(B + (size_t)(k0 + row) * ldb + cq);
            __half2 h01 = __floats2half2_rn(v.x, v.y);
            __half2 h23 = __floats2half2_rn(v.z, v.w);
            *(__half2*)&Bsm[row * B_STRIDE + cq] = h01;
            *(__half2*)&Bsm[row * B_STRIDE + cq + 2] = h23;
        }
        __syncthreads();
#pragma unroll
        for (int kk = 0; kk < 4; kk++) {
            unsigned a0, a1, a2, a3;
            unsigned addrA = smem_u32(&As[(w * 16 + lrow) * A_STRIDE + kk * 16 + lkoff]);
            asm volatile("ldmatrix.sync.aligned.m8n8.x4.shared.b16 {%0,%1,%2,%3}, [%4];"
                         : "=r"(a0), "=r"(a1), "=r"(a2), "=r"(a3) : "r"(addrA));
            for (int nt = 0; nt < nt_cnt; nt++) {
                unsigned b0, b1;
                unsigned addrB = smem_u32(&Bsm[(kk * 16 + lrow) * B_STRIDE + nt * 8]);
                asm volatile("ldmatrix.sync.aligned.m8n8.x2.trans.shared.b16 {%0,%1}, [%2];"
                             : "=r"(b0), "=r"(b1) : "r"(addrB));
                asm volatile("mma.sync.aligned.m16n8k16.row.col.f32.f16.f16.f32 "
                             "{%0,%1,%2,%3}, {%4,%5,%6,%7}, {%8,%9}, {%0,%1,%2,%3};"
                             : "+f"(d[nt][0]), "+f"(d[nt][1]), "+f"(d[nt][2]), "+f"(d[nt][3])
                             : "r"(a0), "r"(a1), "r"(a2), "r"(a3), "r"(b0), "r"(b1));
            }
        }
    }
    float* P = part + (size_t)kz * (N_NODES * 64);
    int g = lane >> 2, q = lane & 3;
    size_t r0 = (size_t)(m0 + w * 16 + g);
    for (int nt = 0; nt < nt_cnt; nt++) {
        int c = coff + nt * 8 + q * 2;
        *(float2*)&P[r0 * 64 + c] = make_float2(d[nt][0], d[nt][1]);
        *(float2*)&P[(r0 + 8) * 64 + c] = make_float2(d[nt][2], d[nt][3]);
    }
}

// ---------------------------------------------------------------------------
// reduce_k: cat = sum of KSPLIT split-K partials; emit per-block cat stats.
// ---------------------------------------------------------------------------
__global__ __launch_bounds__(256) void reduce_k(
    const float* __restrict__ part, float* __restrict__ cat,
    float* __restrict__ stats_c) {
    __shared__ float cs[64], cq[64];
    int by = blockIdx.x;
    int t = threadIdx.x;
    if (t < 64) { cs[t] = 0.0f; cq[t] = 0.0f; }
    __syncthreads();
    int r0 = (t >> 4) * 4;
    int c = (t & 15) * 4;
    float s[4] = {0, 0, 0, 0}, q[4] = {0, 0, 0, 0};
#pragma unroll
    for (int j = 0; j < 4; j++) {
        size_t off = ((size_t)(by * 64 + r0 + j)) * 64 + c;
        float4 v = make_float4(0.f, 0.f, 0.f, 0.f);
#pragma unroll
        for (int p = 0; p < KSPLIT; p++) {
            float4 u = *(const float4*)(part + (size_t)p * (N_NODES * 64) + off);
            v.x += u.x; v.y += u.y; v.z += u.z; v.w += u.w;
        }
        *(float4*)(cat + off) = v;
        s[0] += v.x; q[0] += v.x * v.x;
        s[1] += v.y; q[1] += v.y * v.y;
        s[2] += v.z; q[2] += v.z * v.z;
        s[3] += v.w; q[3] += v.w * v.w;
    }
#pragma unroll
    for (int j = 0; j < 4; j++) {
        atomicAdd(&cs[c + j], s[j]);
        atomicAdd(&cq[c + j], q[j]);
    }
    __syncthreads();
    if (t < 64) {
        stats_c[by * 128 + t] = cs[t];
        stats_c[by * 128 + 64 + t] = cq[t];
    }
}

// ---------------------------------------------------------------------------
// Output GEMM: out += lrelu(bn_out(cat)) @ out_W   [4096,64]x[64,256]
// ---------------------------------------------------------------------------
__global__ __launch_bounds__(256) void gemm_out_k(
    const float* __restrict__ cat, const float* __restrict__ stats_c,
    const float* __restrict__ out_g, const float* __restrict__ out_b,
    const float* __restrict__ outW, float* __restrict__ out) {
    __shared__ float s_sc[64], s_bi[64];
    __shared__ __align__(16) float As[16][65];
    __shared__ __align__(16) float Bs[16][64];
    int t = threadIdx.x;
    bn_fold(stats_c, 64, 64, out_g, out_b, s_sc, s_bi, t, 256);
    int n0 = blockIdx.x * 64;
    int m0 = blockIdx.y * 64;
    int tx = t & 15, ty = t >> 4;
    int lam = t >> 2, lak = (t & 3) << 2;
    int lbk = t >> 4, lbn = (t & 15) << 2;
    float acc[4][4];
#pragma unroll
    for (int r = 0; r < 4; r++)
#pragma unroll
        for (int cc = 0; cc < 4; cc++) acc[r][cc] = 0.0f;
    __syncthreads();

    for (int k0 = 0; k0 < 64; k0 += 16) {
        float4 av = *(const float4*)(cat + (size_t)(m0 + lam) * 64 + k0 + lak);
        float v;
        v = av.x * s_sc[k0 + lak + 0] + s_bi[k0 + lak + 0]; av.x = v > 0.0f ? v : 0.1f * v;
        v = av.y * s_sc[k0 + lak + 1] + s_bi[k0 + lak + 1]; av.y = v > 0.0f ? v : 0.1f * v;
        v = av.z * s_sc[k0 + lak + 2] + s_bi[k0 + lak + 2]; av.z = v > 0.0f ? v : 0.1f * v;
        v = av.w * s_sc[k0 + lak + 3] + s_bi[k0 + lak + 3]; av.w = v > 0.0f ? v : 0.1f * v;
        As[lak + 0][lam] = av.x;
        As[lak + 1][lam] = av.y;
        As[lak + 2][lam] = av.z;
        As[lak + 3][lam] = av.w;
        float4 bv = *(const float4*)(outW + (size_t)(k0 + lbk) * 256 + n0 + lbn);
        *(float4*)&Bs[lbk][lbn] = bv;
        __syncthreads();
#pragma unroll
        for (int kk = 0; kk < 16; kk++) {
            float a0 = As[kk][ty * 4 + 0];
            float a1 = As[kk][ty * 4 + 1];
            float a2 = As[kk][ty * 4 + 2];
            float a3 = As[kk][ty * 4 + 3];
            float4 b = *(const float4*)&Bs[kk][tx * 4];
            acc[0][0] += a0 * b.x; acc[0][1] += a0 * b.y; acc[0][2] += a0 * b.z; acc[0][3] += a0 * b.w;
            acc[1][0] += a1 * b.x; acc[1][1] += a1 * b.y; acc[1][2] += a1 * b.z; acc[1][3] += a1 * b.w;
            acc[2][0] += a2 * b.x; acc[2][1] += a2 * b.y; acc[2][2] += a2 * b.z; acc[2][3] += a2 * b.w;
            acc[3][0] += a3 * b.x; acc[3][1] += a3 * b.y; acc[3][2] += a3 * b.z; acc[3][3] += a3 * b.w;
        }
        __syncthreads();
    }
#pragma unroll
    for (int r = 0; r < 4; r++) {
        size_t m = m0 + ty * 4 + r;
#pragma unroll
        for (int cc = 0; cc < 4; cc++) {
            float* p = out + m * 256 + n0 + tx * 4 + cc;
            *p += acc[r][cc];
        }
    }
}

// ---------------------------------------------------------------------------
// Launch
// ---------------------------------------------------------------------------
extern "C" void kernel_launch(void* const* d_in, const int* in_sizes, int n_in,
                              void* d_out, int out_size) {
    const float* x    = (const float*)d_in[0];
    const float* pos  = (const float*)d_in[1];
    const float* ori  = (const float*)d_in[2];
    const int*   seq  = (const int*)d_in[3];
    // d_in[4] = batch (implied by graph)
    const int* src1 = (const int*)d_in[5];
    const int* dst1 = (const int*)d_in[6];
    // src2/dst2, src3/dst3 unused: nested-radius property recovers them
    const float* id_g = (const float*)d_in[11];
    const float* id_b = (const float*)d_in[12];
    const float* id_W = (const float*)d_in[13];
    const float* in_g = (const float*)d_in[14];
    const float* in_b = (const float*)d_in[15];
    const float* in_W = (const float*)d_in[16];
    const float* mid_g = (const float*)d_in[17];
    const float* mid_b = (const float*)d_in[18];
    const float* Ws1 = (const float*)d_in[19];
    const float* bs1 = (const float*)d_in[20];
    const float* W1  = (const float*)d_in[21];
    const float* Ws2 = (const float*)d_in[22];
    const float* bs2 = (const float*)d_in[23];
    const float* W2  = (const float*)d_in[24];
    const float* Ws3 = (const float*)d_in[25];
    const float* bs3 = (const float*)d_in[26];
    const float* W3  = (const float*)d_in[27];
    const float* out_g = (const float*)d_in[28];
    const float* out_b = (const float*)d_in[29];
    const float* out_W = (const float*)d_in[30];
    float* out = (float*)d_out;

    int E1 = in_sizes[5];

    float *h0, *cat, *part, *stats, *sb;
    __half *agg1, *agg2, *agg3;
    int* ro;
    cudaGetSymbolAddress((void**)&h0, g_h0);
    cudaGetSymbolAddress((void**)&agg1, g_agg1);
    cudaGetSymbolAddress((void**)&agg2, g_agg2);
    cudaGetSymbolAddress((void**)&agg3, g_agg3);
    cudaGetSymbolAddress((void**)&cat, g_cat);
    cudaGetSymbolAddress((void**)&part, g_part);
    cudaGetSymbolAddress((void**)&stats, g_stats);
    cudaGetSymbolAddress((void**)&sb, g_sb);
    cudaGetSymbolAddress((void**)&ro, g_ro);
    float* stats_x = stats;              // 16 slots * 256
    float* stats_h = stats + 4096;       // 64 slots * 128
    float* stats_c = stats + 12288;      // 64 slots * 128

    // 1. x column stats + branch-1 CSR
    prep_k<<<33, 256>>>(x, dst1, E1, stats_x, ro);
    // 2. identity GEMM -> out, input GEMM -> h0 (+ h0 stats)
    gemm_x_k<<<dim3(5, 64), 256>>>(x, stats_x, id_g, id_b, id_W,
                                   in_g, in_b, in_W, out, h0, stats_h);
    // 3. fold mid-BN once
    fold_bn_k<<<1, 64>>>(stats_h, mid_g, mid_b, sb);
    // 4. fused 3-branch edge aggregation, tensor-core Phase C, EB=64
    edge_all_k<<<N_NODES, 256>>>(h0, pos, ori, seq, src1, ro,
                                 Ws1, bs1, Ws2, bs2, Ws3, bs3,
                                 sb, agg1, agg2, agg3);
    // 5. agg GEMMs, tensor-core HMMA, split-K (768 blocks)
    gemm_agg_k<<<dim3(3, 64, KSPLIT), 128>>>(agg1, agg2, agg3, W1, W2, W3, part);
    // 6. reduce partials -> cat (+ cat stats)
    reduce_k<<<64, 256>>>(part, cat, stats_c);
    // 7. output GEMM, accumulate onto identity
    gemm_out_k<<<dim3(4, 64), 256>>>(cat, stats_c, out_g, out_b, out_W, out);
}

// round 15
// speedup vs baseline: 1.3122x; 1.0192x over previous
#include <cuda_runtime.h>
#include <cuda_fp16.h>

// ---------------------------------------------------------------------------
// Problem constants
// ---------------------------------------------------------------------------
#define N_NODES 4096
#define AGGW    1024     // K(16) * WIDTH(64)
#define KSPLIT  4
#define NPB     4        // nodes per edge_all block

__device__ __forceinline__ unsigned smem_u32(const void* p) {
    return (unsigned)__cvta_generic_to_shared(p);
}

// ---------------------------------------------------------------------------
// Scratch (device globals -- no allocation allowed). 16B-aligned for float4.
// ---------------------------------------------------------------------------
__device__ __align__(16) float g_h0[N_NODES * 64];
__device__ __align__(16) __half g_agg1[N_NODES * AGGW];
__device__ __align__(16) __half g_agg2[N_NODES * AGGW];
__device__ __align__(16) __half g_agg3[N_NODES * AGGW];
__device__ __align__(16) float g_cat[N_NODES * 64];
__device__ __align__(16) float g_part[KSPLIT * N_NODES * 64];   // split-K partials
// partial column stats: x: 16 slots * 256 = 4096
//                       h0: 64 slots * 128 = 8192 at offset 4096
//                       cat: 64 slots * 128 = 8192 at offset 12288
__device__ float g_stats[20480];
__device__ float g_sb[128];          // mid-BN folded scale[0:64) / bias[64:128)
__device__ int   g_ro[N_NODES + 1];

// ---------------------------------------------------------------------------
// BN fold: reduce nslots partial (sum, sq) -> per-channel scale/bias in smem
// ---------------------------------------------------------------------------
__device__ __forceinline__ void bn_fold(const float* __restrict__ stats, int C,
                                        int nslots,
                                        const float* __restrict__ g,
                                        const float* __restrict__ b,
                                        float* s_sc, float* s_bi,
                                        int t, int nthreads) {
    for (int c = t; c < C; c += nthreads) {
        float s = 0.0f, q = 0.0f;
        for (int bk = 0; bk < nslots; bk++) {
            s += stats[bk * 2 * C + c];
            q += stats[bk * 2 * C + C + c];
        }
        float m = s * (1.0f / N_NODES);
        float v = q * (1.0f / N_NODES) - m * m;
        float rs = rsqrtf(v + 1e-5f);
        float sc = rs * g[c];
        s_sc[c] = sc;
        s_bi[c] = b[c] - m * sc;
    }
}

// ---------------------------------------------------------------------------
// fold_bn_k: one block, folds the 64-slot h0 stats into g_sb once
// ---------------------------------------------------------------------------
__global__ void fold_bn_k(const float* __restrict__ stats,
                          const float* __restrict__ g,
                          const float* __restrict__ b,
                          float* __restrict__ sb) {
    int c = threadIdx.x;   // 64 threads
    float s = 0.0f, q = 0.0f;
    for (int bk = 0; bk < 64; bk++) {
        s += stats[bk * 128 + c];
        q += stats[bk * 128 + 64 + c];
    }
    float m = s * (1.0f / N_NODES);
    float v = q * (1.0f / N_NODES) - m * m;
    float rs = rsqrtf(v + 1e-5f);
    float sc = rs * g[c];
    sb[c] = sc;
    sb[64 + c] = b[c] - m * sc;
}

// ---------------------------------------------------------------------------
// prep: blocks 0..15 -> partial column stats of x (C=128)
//       blocks 16..32 -> CSR row offsets for branch-1 dst (binary search)
// ---------------------------------------------------------------------------
__global__ void prep_k(const float* __restrict__ x, const int* __restrict__ dst,
                       int E, float* __restrict__ stats_x, int* __restrict__ ro) {
    int bx = blockIdx.x;
    if (bx < 16) {
        int c = threadIdx.x;
        if (c < 128) {
            int r0 = bx * 256;
            float s = 0.0f, s2 = 0.0f;
            for (int r = r0; r < r0 + 256; r++) {
                float v = x[(size_t)r * 128 + c];
                s += v;
                s2 += v * v;
            }
            stats_x[bx * 256 + c] = s;
            stats_x[bx * 256 + 128 + c] = s2;
        }
    } else {
        int t = (bx - 16) * 256 + threadIdx.x;
        if (t > N_NODES) return;
        if (t == N_NODES) { ro[t] = E; return; }
        int lo = 0, hi = E;
        while (lo < hi) {
            int mid = (lo + hi) >> 1;
            if (dst[mid] < t) lo = mid + 1; else hi = mid;
        }
        ro[t] = lo;
    }
}

// ---------------------------------------------------------------------------
// gemm_x: merged identity + input GEMMs on A = x [4096,128].
// ---------------------------------------------------------------------------
__global__ __launch_bounds__(256) void gemm_x_k(
    const float* __restrict__ x, const float* __restrict__ stats_x,
    const float* __restrict__ id_g, const float* __restrict__ id_b,
    const float* __restrict__ idW,
    const float* __restrict__ in_g, const float* __restrict__ in_b,
    const float* __restrict__ inW,
    float* __restrict__ out, float* __restrict__ h0,
    float* __restrict__ stats_h) {
    __shared__ float s_sc[128], s_bi[128];
    __shared__ __align__(16) float As[16][65];
    __shared__ __align__(16) float Bs[16][64];
    __shared__ float hs[64], hq[64];
    int t = threadIdx.x;
    int bx = blockIdx.x;
    bool idp = bx < 4;
    bn_fold(stats_x, 128, 16, idp ? id_g : in_g, idp ? id_b : in_b, s_sc, s_bi, t, 256);

    const float* B = idp ? idW : inW;
    int Nd = idp ? 256 : 64;
    int n0 = idp ? bx * 64 : 0;
    float* C = idp ? out : h0;
    int m0 = blockIdx.y * 64;
    int tx = t & 15, ty = t >> 4;
    int lam = t >> 2, lak = (t & 3) << 2;
    int lbk = t >> 4, lbn = (t & 15) << 2;
    float acc[4][4];
#pragma unroll
    for (int r = 0; r < 4; r++)
#pragma unroll
        for (int cc = 0; cc < 4; cc++) acc[r][cc] = 0.0f;
    if (t < 64) { hs[t] = 0.0f; hq[t] = 0.0f; }
    __syncthreads();

    for (int k0 = 0; k0 < 128; k0 += 16) {
        float4 av = *(const float4*)(x + (size_t)(m0 + lam) * 128 + k0 + lak);
        float v;
        v = av.x * s_sc[k0 + lak + 0] + s_bi[k0 + lak + 0]; av.x = v > 0.0f ? v : 0.1f * v;
        v = av.y * s_sc[k0 + lak + 1] + s_bi[k0 + lak + 1]; av.y = v > 0.0f ? v : 0.1f * v;
        v = av.z * s_sc[k0 + lak + 2] + s_bi[k0 + lak + 2]; av.z = v > 0.0f ? v : 0.1f * v;
        v = av.w * s_sc[k0 + lak + 3] + s_bi[k0 + lak + 3]; av.w = v > 0.0f ? v : 0.1f * v;
        As[lak + 0][lam] = av.x;
        As[lak + 1][lam] = av.y;
        As[lak + 2][lam] = av.z;
        As[lak + 3][lam] = av.w;
        float4 bv = *(const float4*)(B + (size_t)(k0 + lbk) * Nd + n0 + lbn);
        *(float4*)&Bs[lbk][lbn] = bv;
        __syncthreads();
#pragma unroll
        for (int kk = 0; kk < 16; kk++) {
            float a0 = As[kk][ty * 4 + 0];
            float a1 = As[kk][ty * 4 + 1];
            float a2 = As[kk][ty * 4 + 2];
            float a3 = As[kk][ty * 4 + 3];
            float4 b = *(const float4*)&Bs[kk][tx * 4];
            acc[0][0] += a0 * b.x; acc[0][1] += a0 * b.y; acc[0][2] += a0 * b.z; acc[0][3] += a0 * b.w;
            acc[1][0] += a1 * b.x; acc[1][1] += a1 * b.y; acc[1][2] += a1 * b.z; acc[1][3] += a1 * b.w;
            acc[2][0] += a2 * b.x; acc[2][1] += a2 * b.y; acc[2][2] += a2 * b.z; acc[2][3] += a2 * b.w;
            acc[3][0] += a3 * b.x; acc[3][1] += a3 * b.y; acc[3][2] += a3 * b.z; acc[3][3] += a3 * b.w;
        }
        __syncthreads();
    }
#pragma unroll
    for (int r = 0; r < 4; r++) {
        int m = m0 + ty * 4 + r;
#pragma unroll
        for (int cc = 0; cc < 4; cc++)
            C[(size_t)m * Nd + n0 + tx * 4 + cc] = acc[r][cc];
    }
    if (!idp) {
#pragma unroll
        for (int cc = 0; cc < 4; cc++) {
            float s = acc[0][cc] + acc[1][cc] + acc[2][cc] + acc[3][cc];
            float q = acc[0][cc] * acc[0][cc] + acc[1][cc] * acc[1][cc] +
                      acc[2][cc] * acc[2][cc] + acc[3][cc] * acc[3][cc];
            atomicAdd(&hs[tx * 4 + cc], s);
            atomicAdd(&hq[tx * 4 + cc], q);
        }
        __syncthreads();
        if (t < 64) {
            stats_h[blockIdx.y * 128 + t] = hs[t];
            stats_h[blockIdx.y * 128 + 64 + t] = hq[t];
        }
    }
}

// ---------------------------------------------------------------------------
// Fused edge aggregation, TENSOR-CORE Phase C, EB=64, MULTI-NODE blocks:
//   grid N_NODES/NPB; weights/BN staged ONCE per block, NPB nodes looped.
// ---------------------------------------------------------------------------
#define EB 64
#define WST 24    // s_wh row stride in halves
#define HST 72    // s_h row stride in halves
__global__ __launch_bounds__(256) void edge_all_k(
    const float* __restrict__ h0, const float* __restrict__ pos,
    const float* __restrict__ ori, const int* __restrict__ seq,
    const int* __restrict__ src, const int* __restrict__ ro,
    const float* __restrict__ Ws1, const float* __restrict__ bs1,
    const float* __restrict__ Ws2, const float* __restrict__ bs2,
    const float* __restrict__ Ws3, const float* __restrict__ bs3,
    const float* __restrict__ sb,
    __half* __restrict__ agg1, __half* __restrict__ agg2,
    __half* __restrict__ agg3) {
    const double R2SQ = 1.8 * 1.8;
    const double R3T  = 0.75 * 1.8;
    const double R3SQ = R3T * R3T;
    __shared__ float s_sc[64], s_bi[64];
    __shared__ __align__(16) float s_W1[5 * 112];
    __shared__ __align__(16) float s_b1[5 * 16];
    __shared__ __align__(16) float s_W2[7 * 112];
    __shared__ __align__(16) float s_b2[7 * 16];
    __shared__ __align__(16) float s_W3[11 * 112];
    __shared__ __align__(16) float s_b3[11 * 16];
    __shared__ float s_fri[9];
    __shared__ float s_posi[3];
    __shared__ int   s_seqi;
    __shared__ float s_d[EB];
    __shared__ int   s_in2[EB], s_in3[EB];
    __shared__ float s_feat[EB][6];
    __shared__ int   s_ds[EB], s_src[EB];
    __shared__ __align__(16) __half s_wh[3][EB][WST];   // w per branch, [edge][k]
    __shared__ __align__(16) __half s_h[EB][HST];       // h fp16 [edge][c]

    int t = threadIdx.x;
    // stage weights + BN ONCE per block
    if (t < 128) { if (t < 64) s_sc[t] = sb[t]; else s_bi[t - 64] = sb[t]; }
    for (int j = t; j < 5 * 112; j += 256)  s_W1[j] = Ws1[j];
    for (int j = t; j < 5 * 16; j += 256)   s_b1[j] = bs1[j];
    for (int j = t; j < 7 * 112; j += 256)  s_W2[j] = Ws2[j];
    for (int j = t; j < 7 * 16; j += 256)   s_b2[j] = bs2[j];
    for (int j = t; j < 11 * 112; j += 256) s_W3[j] = Ws3[j];
    for (int j = t; j < 11 * 16; j += 256)  s_b3[j] = bs3[j];

    int w = t >> 5, lane = t & 31;
    int aerow = ((lane >> 4) & 1) * 8 + (lane & 7);   // A (.x4.trans): edge row
    int amcol = ((lane >> 3) & 1) * 8;                // A: m col-group (halves)
    int bero = lane & 15;                             // B (.x2.trans): edge row
    int g = lane >> 2, q = lane & 3;

    for (int ni = 0; ni < NPB; ni++) {
        int i = blockIdx.x * NPB + ni;
        // per-node header (13 smem words)
        if (t < 9)  s_fri[t] = ori[i * 9 + t];
        if (t >= 9 && t < 12) s_posi[t - 9] = pos[i * 3 + (t - 9)];
        if (t == 12) s_seqi = seq[i];
        __syncthreads();

        int start = ro[i], end = ro[i + 1];
        float d1[4], d2[4], d3[4];
#pragma unroll
        for (int j = 0; j < 4; j++) { d1[j] = 0.0f; d2[j] = 0.0f; d3[j] = 0.0f; }

        for (int e0 = start; e0 < end; e0 += EB) {
            int ne = min(EB, end - e0);
            // --- Phase A: per-edge geometry (1 thread per edge) ---
            if (t < ne) {
                int js = src[e0 + t];
                s_src[t] = js;
                float dx = __fadd_rn(pos[js * 3 + 0], -s_posi[0]);
                float dy = __fadd_rn(pos[js * 3 + 1], -s_posi[1]);
                float dz = __fadd_rn(pos[js * 3 + 2], -s_posi[2]);
                float d2v = __fadd_rn(__fadd_rn(__fmul_rn(dx, dx), __fmul_rn(dy, dy)),
                                      __fmul_rn(dz, dz));
                double d2d = (double)d2v;
                s_in2[t] = (d2d <= R2SQ) ? 1 : 0;
                s_in3[t] = (d2d <= R3SQ) ? 1 : 0;
                float dist = sqrtf(d2v);
                s_d[t] = dist;
                float inv = 1.0f / (dist + 1e-9f);
                float ux = dx * inv, uy = dy * inv, uz = dz * inv;
                float f0 = s_fri[0], f1 = s_fri[1], f2 = s_fri[2];
                float f3 = s_fri[3], f4 = s_fri[4], f5 = s_fri[5];
                float f6 = s_fri[6], f7 = s_fri[7], f8 = s_fri[8];
                s_feat[t][0] = f0 * ux + f1 * uy + f2 * uz;
                s_feat[t][1] = f3 * ux + f4 * uy + f5 * uz;
                s_feat[t][2] = f6 * ux + f7 * uy + f8 * uz;
                const float* op = ori + (size_t)js * 9;
                s_feat[t][3] = f0 * op[0] + f1 * op[1] + f2 * op[2];
                s_feat[t][4] = f3 * op[3] + f4 * op[4] + f5 * op[5];
                s_feat[t][5] = f6 * op[6] + f7 * op[7] + f8 * op[8];
                s_ds[t] = seq[js] - s_seqi;
            }
            __syncthreads();
            // --- Phase B1 (vectorized): k-pairs with float2 weight loads ---
            for (int task = t; task < ne * 8; task += 256) {    // branch 1
                int e = task >> 3, kq = (task & 7) << 1;
                int dd = s_ds[e]; dd = max(-2, min(2, dd));
                const float* wr = s_W1 + (dd + 2) * 112 + kq;
                float2 sv = *(const float2*)(s_b1 + (dd + 2) * 16 + kq);
                float dscale = s_d[e] / 2.7f;
                float2 wv = *(const float2*)(wr);
                sv.x += dscale * wv.x; sv.y += dscale * wv.y;
#pragma unroll
                for (int cc = 0; cc < 6; cc++) {
                    float f = s_feat[e][cc];
                    wv = *(const float2*)(wr + (cc + 1) * 16);
                    sv.x += f * wv.x; sv.y += f * wv.y;
                }
                sv.x = sv.x > 0.0f ? sv.x : 0.2f * sv.x;
                sv.y = sv.y > 0.0f ? sv.y : 0.2f * sv.y;
                *(__half2*)&s_wh[0][e][kq] = __floats2half2_rn(sv.x, sv.y);
            }
            for (int task = t; task < ne * 8; task += 256) {    // branch 2
                int e = task >> 3, kq = (task & 7) << 1;
                float2 sv = make_float2(0.0f, 0.0f);
                if (s_in2[e]) {
                    int dd = s_ds[e]; dd = max(-3, min(3, dd));
                    const float* wr = s_W2 + (dd + 3) * 112 + kq;
                    sv = *(const float2*)(s_b2 + (dd + 3) * 16 + kq);
                    float dscale = s_d[e] / 1.8f;
                    float2 wv = *(const float2*)(wr);
                    sv.x += dscale * wv.x; sv.y += dscale * wv.y;
#pragma unroll
                    for (int cc = 0; cc < 6; cc++) {
                        float f = s_feat[e][cc];
                        wv = *(const float2*)(wr + (cc + 1) * 16);
                        sv.x += f * wv.x; sv.y += f * wv.y;
                    }
                    sv.x = sv.x > 0.0f ? sv.x : 0.2f * sv.x;
                    sv.y = sv.y > 0.0f ? sv.y : 0.2f * sv.y;
                }
                *(__half2*)&s_wh[1][e][kq] = __floats2half2_rn(sv.x, sv.y);
            }
            for (int task = t; task < ne * 8; task += 256) {    // branch 3
                int e = task >> 3, kq = (task & 7) << 1;
                float2 sv = make_float2(0.0f, 0.0f);
                if (s_in3[e]) {
                    int dd = s_ds[e]; dd = max(-5, min(5, dd));
                    const float* wr = s_W3 + (dd + 5) * 112 + kq;
                    sv = *(const float2*)(s_b3 + (dd + 5) * 16 + kq);
                    float dscale = s_d[e] / 1.35f;
                    float2 wv = *(const float2*)(wr);
                    sv.x += dscale * wv.x; sv.y += dscale * wv.y;
#pragma unroll
                    for (int cc = 0; cc < 6; cc++) {
                        float f = s_feat[e][cc];
                        wv = *(const float2*)(wr + (cc + 1) * 16);
                        sv.x += f * wv.x; sv.y += f * wv.y;
                    }
                    sv.x = sv.x > 0.0f ? sv.x : 0.2f * sv.x;
                    sv.y = sv.y > 0.0f ? sv.y : 0.2f * sv.y;
                }
                *(__half2*)&s_wh[2][e][kq] = __floats2half2_rn(sv.x, sv.y);
            }
            // --- Phase B2: gather h0 rows, BN + lrelu, fp16 smem ---
            for (int task = t; task < ne * 16; task += 256) {
                int e = task >> 4, qq = task & 15;
                int cc = qq << 2;
                float4 v = *(const float4*)(h0 + (size_t)s_src[e] * 64 + cc);
                float u;
                u = v.x * s_sc[cc + 0] + s_bi[cc + 0]; v.x = u > 0.0f ? u : 0.1f * u;
                u = v.y * s_sc[cc + 1] + s_bi[cc + 1]; v.y = u > 0.0f ? u : 0.1f * u;
                u = v.z * s_sc[cc + 2] + s_bi[cc + 2]; v.z = u > 0.0f ? u : 0.1f * u;
                u = v.w * s_sc[cc + 3] + s_bi[cc + 3]; v.w = u > 0.0f ? u : 0.1f * u;
                union { __half2 h2[2]; uint2 uu; } cv;
                cv.h2[0] = __floats2half2_rn(v.x, v.y);
                cv.h2[1] = __floats2half2_rn(v.z, v.w);
                *(uint2*)&s_h[e][cc] = cv.uu;
            }
            // zero-fill padding edges (partial last tile)
            for (int task = t; task < (EB - ne) * 16; task += 256) {
                int e = ne + (task >> 4), qq = task & 15;
                *(uint2*)&s_h[e][qq << 2] = make_uint2(0u, 0u);
                s_wh[0][e][qq] = __float2half_rn(0.0f);
                s_wh[1][e][qq] = __float2half_rn(0.0f);
                s_wh[2][e][qq] = __float2half_rn(0.0f);
            }
            __syncthreads();
            // --- Phase C: tensor-core accumulate (4 chunks of 16 edges) ---
#pragma unroll
            for (int ch = 0; ch < 4; ch++) {
                int ec = ch * 16;
                unsigned b0, b1;
                unsigned addrB = smem_u32(&s_h[ec + bero][w * 8]);
                asm volatile("ldmatrix.sync.aligned.m8n8.x2.trans.shared.b16 {%0,%1}, [%2];"
                             : "=r"(b0), "=r"(b1) : "r"(addrB));
                unsigned a0, a1, a2, a3;
                unsigned addrA = smem_u32(&s_wh[0][ec + aerow][amcol]);
                asm volatile("ldmatrix.sync.aligned.m8n8.x4.trans.shared.b16 {%0,%1,%2,%3}, [%4];"
                             : "=r"(a0), "=r"(a1), "=r"(a2), "=r"(a3) : "r"(addrA));
                asm volatile("mma.sync.aligned.m16n8k16.row.col.f32.f16.f16.f32 "
                             "{%0,%1,%2,%3}, {%4,%5,%6,%7}, {%8,%9}, {%0,%1,%2,%3};"
                             : "+f"(d1[0]), "+f"(d1[1]), "+f"(d1[2]), "+f"(d1[3])
                             : "r"(a0), "r"(a1), "r"(a2), "r"(a3), "r"(b0), "r"(b1));
                addrA = smem_u32(&s_wh[1][ec + aerow][amcol]);
                asm volatile("ldmatrix.sync.aligned.m8n8.x4.trans.shared.b16 {%0,%1,%2,%3}, [%4];"
                             : "=r"(a0), "=r"(a1), "=r"(a2), "=r"(a3) : "r"(addrA));
                asm volatile("mma.sync.aligned.m16n8k16.row.col.f32.f16.f16.f32 "
                             "{%0,%1,%2,%3}, {%4,%5,%6,%7}, {%8,%9}, {%0,%1,%2,%3};"
                             : "+f"(d2[0]), "+f"(d2[1]), "+f"(d2[2]), "+f"(d2[3])
                             : "r"(a0), "r"(a1), "r"(a2), "r"(a3), "r"(b0), "r"(b1));
                addrA = smem_u32(&s_wh[2][ec + aerow][amcol]);
                asm volatile("ldmatrix.sync.aligned.m8n8.x4.trans.shared.b16 {%0,%1,%2,%3}, [%4];"
                             : "=r"(a0), "=r"(a1), "=r"(a2), "=r"(a3) : "r"(addrA));
                asm volatile("mma.sync.aligned.m16n8k16.row.col.f32.f16.f16.f32 "
                             "{%0,%1,%2,%3}, {%4,%5,%6,%7}, {%8,%9}, {%0,%1,%2,%3};"
                             : "+f"(d3[0]), "+f"(d3[1]), "+f"(d3[2]), "+f"(d3[3])
                             : "r"(a0), "r"(a1), "r"(a2), "r"(a3), "r"(b0), "r"(b1));
            }
            __syncthreads();
        }
        // writeout: frag (rows g, g+8; cols w*8 + 2q, +1)
        size_t base = (size_t)i * AGGW;
        int c = w * 8 + q * 2;
        *(__half2*)(agg1 + base + (size_t)g * 64 + c)       = __floats2half2_rn(d1[0], d1[1]);
        *(__half2*)(agg1 + base + (size_t)(g + 8) * 64 + c) = __floats2half2_rn(d1[2], d1[3]);
        *(__half2*)(agg2 + base + (size_t)g * 64 + c)       = __floats2half2_rn(d2[0], d2[1]);
        *(__half2*)(agg2 + base + (size_t)(g + 8) * 64 + c) = __floats2half2_rn(d2[2], d2[3]);
        *(__half2*)(agg3 + base + (size_t)g * 64 + c)       = __floats2half2_rn(d3[0], d3[1]);
        *(__half2*)(agg3 + base + (size_t)(g + 8) * 64 + c) = __floats2half2_rn(d3[2], d3[3]);
    }
}

// ---------------------------------------------------------------------------
// agg GEMMs, TENSOR CORE (HMMA m16n8k16), split-K (validated R11).
// ---------------------------------------------------------------------------
#define A_STRIDE 72
#define B_STRIDE 40
__global__ __launch_bounds__(128) void gemm_agg_k(
    const __half* __restrict__ agg1, const __half* __restrict__ agg2,
    const __half* __restrict__ agg3,
    const float* __restrict__ W1, const float* __restrict__ W2,
    const float* __restrict__ W3, float* __restrict__ part) {
    __shared__ __align__(16) __half As[64 * A_STRIDE];
    __shared__ __align__(16) __half Bsm[64 * B_STRIDE];
    int bx = blockIdx.x;
    int m0 = blockIdx.y * 64;
    int kz = blockIdx.z;
    const __half* A; const float* B; int ldb, coff, BN;
    if (bx == 0)      { A = agg1; B = W1; ldb = 32; coff = 0;  BN = 32; }
    else if (bx == 1) { A = agg2; B = W2; ldb = 16; coff = 32; BN = 16; }
    else              { A = agg3; B = W3; ldb = 16; coff = 48; BN = 16; }
    int t = threadIdx.x;
    int w = t >> 5, lane = t & 31;
    int nt_cnt = BN >> 3;
    float d[4][4];
#pragma unroll
    for (int i = 0; i < 4; i++)
#pragma unroll
        for (int j = 0; j < 4; j++) d[i][j] = 0.0f;
    int kbase = kz * (1024 / KSPLIT);

    int aseg = t & 7;
    int arow0 = t >> 3;
    int nf = ldb >> 2;
    int lrow = lane & 15;
    int lkoff = (lane >> 4) * 8;

    for (int ks = 0; ks < 1024 / KSPLIT; ks += 64) {
        int k0 = kbase + ks;
        __syncthreads();
#pragma unroll
        for (int j = 0; j < 4; j++) {
            int row = j * 16 + arow0;
            uint4 v = *(const uint4*)(A + (size_t)(m0 + row) * 1024 + k0 + aseg * 8);
            *(uint4*)&As[row * A_STRIDE + aseg * 8] = v;
        }
        for (int idx = t; idx < 64 * nf; idx += 128) {
            int row = idx / nf, cq = (idx % nf) << 2;
            float4 v = *(const float4*)(B + (size_t)(k0 + row) * ldb + cq);
            __half2 h01 = __floats2half2_rn(v.x, v.y);
            __half2 h23 = __floats2half2_rn(v.z, v.w);
            *(__half2*)&Bsm[row * B_STRIDE + cq] = h01;
            *(__half2*)&Bsm[row * B_STRIDE + cq + 2] = h23;
        }
        __syncthreads();
#pragma unroll
        for (int kk = 0; kk < 4; kk++) {
            unsigned a0, a1, a2, a3;
            unsigned addrA = smem_u32(&As[(w * 16 + lrow) * A_STRIDE + kk * 16 + lkoff]);
            asm volatile("ldmatrix.sync.aligned.m8n8.x4.shared.b16 {%0,%1,%2,%3}, [%4];"
                         : "=r"(a0), "=r"(a1), "=r"(a2), "=r"(a3) : "r"(addrA));
            for (int nt = 0; nt < nt_cnt; nt++) {
                unsigned b0, b1;
                unsigned addrB = smem_u32(&Bsm[(kk * 16 + lrow) * B_STRIDE + nt * 8]);
                asm volatile("ldmatrix.sync.aligned.m8n8.x2.trans.shared.b16 {%0,%1}, [%2];"
                             : "=r"(b0), "=r"(b1) : "r"(addrB));
                asm volatile("mma.sync.aligned.m16n8k16.row.col.f32.f16.f16.f32 "
                             "{%0,%1,%2,%3}, {%4,%5,%6,%7}, {%8,%9}, {%0,%1,%2,%3};"
                             : "+f"(d[nt][0]), "+f"(d[nt][1]), "+f"(d[nt][2]), "+f"(d[nt][3])
                             : "r"(a0), "r"(a1), "r"(a2), "r"(a3), "r"(b0), "r"(b1));
            }
        }
    }
    float* P = part + (size_t)kz * (N_NODES * 64);
    int g = lane >> 2, q = lane & 3;
    size_t r0 = (size_t)(m0 + w * 16 + g);
    for (int nt = 0; nt < nt_cnt; nt++) {
        int c = coff + nt * 8 + q * 2;
        *(float2*)&P[r0 * 64 + c] = make_float2(d[nt][0], d[nt][1]);
        *(float2*)&P[(r0 + 8) * 64 + c] = make_float2(d[nt][2], d[nt][3]);
    }
}

// ---------------------------------------------------------------------------
// reduce_k: cat = sum of KSPLIT split-K partials; emit per-block cat stats.
// ---------------------------------------------------------------------------
__global__ __launch_bounds__(256) void reduce_k(
    const float* __restrict__ part, float* __restrict__ cat,
    float* __restrict__ stats_c) {
    __shared__ float cs[64], cq[64];
    int by = blockIdx.x;
    int t = threadIdx.x;
    if (t < 64) { cs[t] = 0.0f; cq[t] = 0.0f; }
    __syncthreads();
    int r0 = (t >> 4) * 4;
    int c = (t & 15) * 4;
    float s[4] = {0, 0, 0, 0}, q[4] = {0, 0, 0, 0};
#pragma unroll
    for (int j = 0; j < 4; j++) {
        size_t off = ((size_t)(by * 64 + r0 + j)) * 64 + c;
        float4 v = make_float4(0.f, 0.f, 0.f, 0.f);
#pragma unroll
        for (int p = 0; p < KSPLIT; p++) {
            float4 u = *(const float4*)(part + (size_t)p * (N_NODES * 64) + off);
            v.x += u.x; v.y += u.y; v.z += u.z; v.w += u.w;
        }
        *(float4*)(cat + off) = v;
        s[0] += v.x; q[0] += v.x * v.x;
        s[1] += v.y; q[1] += v.y * v.y;
        s[2] += v.z; q[2] += v.z * v.z;
        s[3] += v.w; q[3] += v.w * v.w;
    }
#pragma unroll
    for (int j = 0; j < 4; j++) {
        atomicAdd(&cs[c + j], s[j]);
        atomicAdd(&cq[c + j], q[j]);
    }
    __syncthreads();
    if (t < 64) {
        stats_c[by * 128 + t] = cs[t];
        stats_c[by * 128 + 64 + t] = cq[t];
    }
}

// ---------------------------------------------------------------------------
// Output GEMM: out += lrelu(bn_out(cat)) @ out_W   [4096,64]x[64,256]
// ---------------------------------------------------------------------------
__global__ __launch_bounds__(256) void gemm_out_k(
    const float* __restrict__ cat, const float* __restrict__ stats_c,
    const float* __restrict__ out_g, const float* __restrict__ out_b,
    const float* __restrict__ outW, float* __restrict__ out) {
    __shared__ float s_sc[64], s_bi[64];
    __shared__ __align__(16) float As[16][65];
    __shared__ __align__(16) float Bs[16][64];
    int t = threadIdx.x;
    bn_fold(stats_c, 64, 64, out_g, out_b, s_sc, s_bi, t, 256);
    int n0 = blockIdx.x * 64;
    int m0 = blockIdx.y * 64;
    int tx = t & 15, ty = t >> 4;
    int lam = t >> 2, lak = (t & 3) << 2;
    int lbk = t >> 4, lbn = (t & 15) << 2;
    float acc[4][4];
#pragma unroll
    for (int r = 0; r < 4; r++)
#pragma unroll
        for (int cc = 0; cc < 4; cc++) acc[r][cc] = 0.0f;
    __syncthreads();

    for (int k0 = 0; k0 < 64; k0 += 16) {
        float4 av = *(const float4*)(cat + (size_t)(m0 + lam) * 64 + k0 + lak);
        float v;
        v = av.x * s_sc[k0 + lak + 0] + s_bi[k0 + lak + 0]; av.x = v > 0.0f ? v : 0.1f * v;
        v = av.y * s_sc[k0 + lak + 1] + s_bi[k0 + lak + 1]; av.y = v > 0.0f ? v : 0.1f * v;
        v = av.z * s_sc[k0 + lak + 2] + s_bi[k0 + lak + 2]; av.z = v > 0.0f ? v : 0.1f * v;
        v = av.w * s_sc[k0 + lak + 3] + s_bi[k0 + lak + 3]; av.w = v > 0.0f ? v : 0.1f * v;
        As[lak + 0][lam] = av.x;
        As[lak + 1][lam] = av.y;
        As[lak + 2][lam] = av.z;
        As[lak + 3][lam] = av.w;
        float4 bv = *(const float4*)(outW + (size_t)(k0 + lbk) * 256 + n0 + lbn);
        *(float4*)&Bs[lbk][lbn] = bv;
        __syncthreads();
#pragma unroll
        for (int kk = 0; kk < 16; kk++) {
            float a0 = As[kk][ty * 4 + 0];
            float a1 = As[kk][ty * 4 + 1];
            float a2 = As[kk][ty * 4 + 2];
            float a3 = As[kk][ty * 4 + 3];
            float4 b = *(const float4*)&Bs[kk][tx * 4];
            acc[0][0] += a0 * b.x; acc[0][1] += a0 * b.y; acc[0][2] += a0 * b.z; acc[0][3] += a0 * b.w;
            acc[1][0] += a1 * b.x; acc[1][1] += a1 * b.y; acc[1][2] += a1 * b.z; acc[1][3] += a1 * b.w;
            acc[2][0] += a2 * b.x; acc[2][1] += a2 * b.y; acc[2][2] += a2 * b.z; acc[2][3] += a2 * b.w;
            acc[3][0] += a3 * b.x; acc[3][1] += a3 * b.y; acc[3][2] += a3 * b.z; acc[3][3] += a3 * b.w;
        }
        __syncthreads();
    }
#pragma unroll
    for (int r = 0; r < 4; r++) {
        size_t m = m0 + ty * 4 + r;
#pragma unroll
        for (int cc = 0; cc < 4; cc++) {
            float* p = out + m * 256 + n0 + tx * 4 + cc;
            *p += acc[r][cc];
        }
    }
}

// ---------------------------------------------------------------------------
// Launch
// ---------------------------------------------------------------------------
extern "C" void kernel_launch(void* const* d_in, const int* in_sizes, int n_in,
                              void* d_out, int out_size) {
    const float* x    = (const float*)d_in[0];
    const float* pos  = (const float*)d_in[1];
    const float* ori  = (const float*)d_in[2];
    const int*   seq  = (const int*)d_in[3];
    // d_in[4] = batch (implied by graph)
    const int* src1 = (const int*)d_in[5];
    const int* dst1 = (const int*)d_in[6];
    // src2/dst2, src3/dst3 unused: nested-radius property recovers them
    const float* id_g = (const float*)d_in[11];
    const float* id_b = (const float*)d_in[12];
    const float* id_W = (const float*)d_in[13];
    const float* in_g = (const float*)d_in[14];
    const float* in_b = (const float*)d_in[15];
    const float* in_W = (const float*)d_in[16];
    const float* mid_g = (const float*)d_in[17];
    const float* mid_b = (const float*)d_in[18];
    const float* Ws1 = (const float*)d_in[19];
    const float* bs1 = (const float*)d_in[20];
    const float* W1  = (const float*)d_in[21];
    const float* Ws2 = (const float*)d_in[22];
    const float* bs2 = (const float*)d_in[23];
    const float* W2  = (const float*)d_in[24];
    const float* Ws3 = (const float*)d_in[25];
    const float* bs3 = (const float*)d_in[26];
    const float* W3  = (const float*)d_in[27];
    const float* out_g = (const float*)d_in[28];
    const float* out_b = (const float*)d_in[29];
    const float* out_W = (const float*)d_in[30];
    float* out = (float*)d_out;

    int E1 = in_sizes[5];

    float *h0, *cat, *part, *stats, *sb;
    __half *agg1, *agg2, *agg3;
    int* ro;
    cudaGetSymbolAddress((void**)&h0, g_h0);
    cudaGetSymbolAddress((void**)&agg1, g_agg1);
    cudaGetSymbolAddress((void**)&agg2, g_agg2);
    cudaGetSymbolAddress((void**)&agg3, g_agg3);
    cudaGetSymbolAddress((void**)&cat, g_cat);
    cudaGetSymbolAddress((void**)&part, g_part);
    cudaGetSymbolAddress((void**)&stats, g_stats);
    cudaGetSymbolAddress((void**)&sb, g_sb);
    cudaGetSymbolAddress((void**)&ro, g_ro);
    float* stats_x = stats;              // 16 slots * 256
    float* stats_h = stats + 4096;       // 64 slots * 128
    float* stats_c = stats + 12288;      // 64 slots * 128

    // 1. x column stats + branch-1 CSR
    prep_k<<<33, 256>>>(x, dst1, E1, stats_x, ro);
    // 2. identity GEMM -> out, input GEMM -> h0 (+ h0 stats)
    gemm_x_k<<<dim3(5, 64), 256>>>(x, stats_x, id_g, id_b, id_W,
                                   in_g, in_b, in_W, out, h0, stats_h);
    // 3. fold mid-BN once
    fold_bn_k<<<1, 64>>>(stats_h, mid_g, mid_b, sb);
    // 4. fused 3-branch edge aggregation, tensor-core Phase C, 4 nodes/block
    edge_all_k<<<N_NODES / NPB, 256>>>(h0, pos, ori, seq, src1, ro,
                                       Ws1, bs1, Ws2, bs2, Ws3, bs3,
                                       sb, agg1, agg2, agg3);
    // 5. agg GEMMs, tensor-core HMMA, split-K (768 blocks)
    gemm_agg_k<<<dim3(3, 64, KSPLIT), 128>>>(agg1, agg2, agg3, W1, W2, W3, part);
    // 6. reduce partials -> cat (+ cat stats)
    reduce_k<<<64, 256>>>(part, cat, stats_c);
    // 7. output GEMM, accumulate onto identity
    gemm_out_k<<<dim3(4, 64), 256>>>(cat, stats_c, out_g, out_b, out_W, out);
}